// round 11
// baseline (speedup 1.0000x reference)
#include <cuda_runtime.h>
#include <math.h>
#include <stdint.h>

#define SS 256
#define BB 128
#define HH 512
#define GG 1536
#define EE 192
#define DD1 1024
#define SB (SS*BB)   // 32768
#define PAD 20       // smem row stride in floats (conflict-free: 20r mod 32 distinct)

// ---------------- scratch (__device__ globals, no allocation) ----------------
__device__ float g_x0 [SB*EE];
__device__ float g_xgf[SB*GG];
__device__ float g_xgb[SB*GG];
__device__ float g_y0 [SB*DD1];
__device__ float g_y1 [SB*DD1];
__device__ float g_h0 [2*BB*HH];
__device__ float g_h1 [2*BB*HH];
__device__ float g_an [BB*SS*SS];
__device__ float g_dinv[BB*SS];
__device__ float g_node [BB*SS*HH];
__device__ float g_node2[BB*SS*HH];
__device__ float g_ni   [BB*SS*HH];
__device__ float g_tmp  [BB*SS*HH];
__device__ float g_nodeT[BB*HH*SS];

// group-barrier state (4 groups of 32 CTAs; self-consistent across replays)
__device__ unsigned g_bc[128];
__device__ volatile unsigned g_bs[128];

__device__ __forceinline__ float cvt_tf32(float x) {
    uint32_t r;
    asm("cvt.rna.tf32.f32 %0, %1;" : "=r"(r) : "f"(x));
    return __uint_as_float(r);
}

// ---------------- small elementwise kernels ----------------
__global__ void embed_kernel(const int* __restrict__ i1, const int* __restrict__ i2,
                             const float* __restrict__ emb1, const float* __restrict__ emb2,
                             float* __restrict__ x0) {
    int idx = blockIdx.x * blockDim.x + threadIdx.x;
    if (idx >= SB * EE) return;
    int t = idx / EE, e = idx - t * EE;
    if (e < 128) {
        x0[idx] = emb1[(size_t)i1[t] * 128 + e];
    } else {
        int v = i2[t];
        x0[idx] = (v == 0) ? 0.f : emb2[(size_t)v * 64 + (e - 128)];
    }
}

__global__ void dinv_kernel(const int* __restrict__ pg, float* __restrict__ dinv) {
    int row  = blockIdx.x * 8 + (threadIdx.x >> 5);
    int lane = threadIdx.x & 31;
    int b = row >> 8, s = row & 255;
    const int* ar = pg + ((size_t)b * 3 + 2) * (SS * SS) + (size_t)s * SS;
    int acc = 0;
    for (int t = lane; t < SS; t += 32) acc += ar[t];
    #pragma unroll
    for (int o = 16; o; o >>= 1) acc += __shfl_down_sync(0xffffffffu, acc, o);
    if (lane == 0) dinv[row] = rsqrtf((float)acc + 1.0f);
}

__global__ void an_kernel(const int* __restrict__ pg, const float* __restrict__ dinv,
                          float* __restrict__ an) {
    int idx = blockIdx.x * blockDim.x + threadIdx.x;
    if (idx >= BB * SS * SS) return;
    int t = idx & 255, s = (idx >> 8) & 255, b = idx >> 16;
    float a = (float)pg[((size_t)b * 3 + 2) * (SS * SS) + s * SS + t] + (s == t ? 1.f : 0.f);
    an[idx] = a * dinv[b * SS + s] * dinv[b * SS + t];
}

__global__ void sumdir_kernel(const float* __restrict__ y, float* __restrict__ node) {
    int idx = blockIdx.x * blockDim.x + threadIdx.x;
    if (idx >= BB * SS * HH) return;
    int j = idx & 511, s = (idx >> 9) & 255, b = idx >> 17;
    size_t yi = ((size_t)s * BB + b) * DD1 + j;
    node[idx] = y[yi] + y[yi + HH];
}

__global__ void transpose_out_kernel(const float* __restrict__ node, float* __restrict__ out) {
    int idx = blockIdx.x * blockDim.x + threadIdx.x;
    if (idx >= SS * BB * HH) return;
    int j = idx & 511, b = (idx >> 9) & 127, s = idx >> 16;
    out[idx] = node[((size_t)b * SS + s) * HH + j];
}

// [B,S,H] -> [B,H,S]
__global__ void transpose_bsh(const float* __restrict__ src, float* __restrict__ dst) {
    __shared__ float t[32][33];
    int b = blockIdx.z;
    int s0 = blockIdx.y * 32, h0 = blockIdx.x * 32;
    src += (size_t)b * SS * HH;
    dst += (size_t)b * SS * HH;
    int x = threadIdx.x, y = threadIdx.y;
    #pragma unroll
    for (int i = 0; i < 32; i += 8) t[y + i][x] = src[(size_t)(s0 + y + i) * HH + h0 + x];
    __syncthreads();
    #pragma unroll
    for (int i = 0; i < 32; i += 8) dst[(size_t)(h0 + y + i) * SS + s0 + x] = t[x][y + i];
}

// ================= tf32 mma helpers =================
__device__ __forceinline__ void mma8(float* d, uint32_t a0, uint32_t a1, uint32_t a2,
                                     uint32_t a3, uint32_t b0, uint32_t b1) {
    asm volatile(
        "mma.sync.aligned.m16n8k8.row.col.f32.tf32.tf32.f32 "
        "{%0,%1,%2,%3}, {%4,%5,%6,%7}, {%8,%9}, {%0,%1,%2,%3};"
        : "+f"(d[0]), "+f"(d[1]), "+f"(d[2]), "+f"(d[3])
        : "r"(a0), "r"(a1), "r"(a2), "r"(a3), "r"(b0), "r"(b1));
}
#define FU(x) __float_as_uint(x)

__device__ __forceinline__ void mma_tf32(float* d, const float* a, const float* b) {
    asm volatile(
        "mma.sync.aligned.m16n8k8.row.col.f32.tf32.tf32.f32 "
        "{%0,%1,%2,%3}, {%4,%5,%6,%7}, {%8,%9}, {%0,%1,%2,%3};"
        : "+f"(d[0]), "+f"(d[1]), "+f"(d[2]), "+f"(d[3])
        : "r"(__float_as_uint(a[0])), "r"(__float_as_uint(a[1])),
          "r"(__float_as_uint(a[2])), "r"(__float_as_uint(a[3])),
          "r"(__float_as_uint(b[0])), "r"(__float_as_uint(b[1])));
}

// ============ tf32 mma.sync NT GEMM — CTA tile 128x256, warp tile 64x64 ============
// C[m,n] = sum_k A[m,k]*W[n,k] (+bias, +relu).
// A split: k<K1 from A, k>=K1 from A2 (same lda).
// N split: n0>=Nsplit -> W2/bias2/C2, n0-=Nsplit (fuses two GEMMs sharing A).
// Same proven PAD=20 float4 SMEM layout; only the tile shape changed:
// 8 warps (2m x 4n), 64x64 warp tile -> 32 LDS.32 per 32 MMAs per k8 (was 24/16).
template<bool RELU>
__global__ void __launch_bounds__(256) mma_gemm_nt(
    const float* __restrict__ A, const float* __restrict__ A2,
    const float* __restrict__ W, const float* __restrict__ W2,
    const float* __restrict__ bias, const float* __restrict__ bias2,
    float* __restrict__ C, float* __restrict__ C2,
    int K, int K1, int Nsplit, int lda, int ldw, int ldc,
    long long sA, long long sW, long long sC)
{
    __shared__ float As[128 * PAD];
    __shared__ float Ws[256 * PAD];

    int tid = threadIdx.x;
    int lane = tid & 31, warp = tid >> 5;
    int wm = warp >> 2, wn = warp & 3;          // 2m x 4n
    int groupID = lane >> 2, tig = lane & 3;
    int n0 = blockIdx.x * 256, m0 = blockIdx.y * 128;
    if (W2 && n0 >= Nsplit) {
        W = W2; bias = bias2; C = C2; n0 -= Nsplit;
    }
    int z = blockIdx.z;
    A += (size_t)z * (size_t)sA;
    W += (size_t)z * (size_t)sW;
    C += (size_t)z * (size_t)sC;

    int lr = tid >> 2;            // 0..63
    int lc = (tid & 3) * 4;       // 0,4,8,12

    const int arb = wm * 64;      // warp A row base (64-row tile)
    const int wcb = wn * 64;      // warp W row base (64-col tile)

    float acc[4][8][4];
    #pragma unroll
    for (int mt = 0; mt < 4; mt++)
        #pragma unroll
        for (int nt = 0; nt < 8; nt++)
            #pragma unroll
            for (int q = 0; q < 4; q++) acc[mt][nt][q] = 0.f;

    float4 pa0, pa1, pw0, pw1, pw2, pw3;

    auto gload = [&](int c) {
        int koff = c * 16 + lc;
        const float* Ab;
        if (A2 && koff >= K1)
            Ab = A2 + (size_t)(m0 + lr) * lda + (koff - K1);
        else
            Ab = A + (size_t)(m0 + lr) * lda + koff;
        const float* Wb = W + (size_t)(n0 + lr) * ldw + c * 16 + lc;
        pa0 = *(const float4*)Ab;
        pa1 = *(const float4*)(Ab + (size_t)64 * lda);
        pw0 = *(const float4*)Wb;
        pw1 = *(const float4*)(Wb + (size_t)64 * ldw);
        pw2 = *(const float4*)(Wb + (size_t)128 * ldw);
        pw3 = *(const float4*)(Wb + (size_t)192 * ldw);
    };

    int Cn = K >> 4;
    gload(0);

    for (int c = 0; c < Cn; c++) {
        *(float4*)&As[lr * PAD + lc] =
            make_float4(cvt_tf32(pa0.x), cvt_tf32(pa0.y), cvt_tf32(pa0.z), cvt_tf32(pa0.w));
        *(float4*)&As[(lr + 64) * PAD + lc] =
            make_float4(cvt_tf32(pa1.x), cvt_tf32(pa1.y), cvt_tf32(pa1.z), cvt_tf32(pa1.w));
        *(float4*)&Ws[lr * PAD + lc] =
            make_float4(cvt_tf32(pw0.x), cvt_tf32(pw0.y), cvt_tf32(pw0.z), cvt_tf32(pw0.w));
        *(float4*)&Ws[(lr + 64) * PAD + lc] =
            make_float4(cvt_tf32(pw1.x), cvt_tf32(pw1.y), cvt_tf32(pw1.z), cvt_tf32(pw1.w));
        *(float4*)&Ws[(lr + 128) * PAD + lc] =
            make_float4(cvt_tf32(pw2.x), cvt_tf32(pw2.y), cvt_tf32(pw2.z), cvt_tf32(pw2.w));
        *(float4*)&Ws[(lr + 192) * PAD + lc] =
            make_float4(cvt_tf32(pw3.x), cvt_tf32(pw3.y), cvt_tf32(pw3.z), cvt_tf32(pw3.w));
        __syncthreads();

        if (c + 1 < Cn) gload(c + 1);

        #pragma unroll
        for (int ks = 0; ks < 2; ks++) {
            int k0 = ks * 8;
            float af[4][4], bf[8][2];
            #pragma unroll
            for (int mt = 0; mt < 4; mt++) {
                int rb = arb + mt * 16 + groupID;
                af[mt][0] = As[rb * PAD + k0 + tig];
                af[mt][1] = As[(rb + 8) * PAD + k0 + tig];
                af[mt][2] = As[rb * PAD + k0 + 4 + tig];
                af[mt][3] = As[(rb + 8) * PAD + k0 + 4 + tig];
            }
            #pragma unroll
            for (int nt = 0; nt < 8; nt++) {
                int cb = wcb + nt * 8 + groupID;
                bf[nt][0] = Ws[cb * PAD + k0 + tig];
                bf[nt][1] = Ws[cb * PAD + k0 + 4 + tig];
            }
            #pragma unroll
            for (int mt = 0; mt < 4; mt++)
                #pragma unroll
                for (int nt = 0; nt < 8; nt++)
                    mma_tf32(acc[mt][nt], af[mt], bf[nt]);
        }
        __syncthreads();
    }

    #pragma unroll
    for (int mt = 0; mt < 4; mt++) {
        #pragma unroll
        for (int nt = 0; nt < 8; nt++) {
            int gr = m0 + arb + mt * 16 + groupID;
            int gc = n0 + wcb + nt * 8 + tig * 2;
            float b0 = 0.f, b1 = 0.f;
            if (bias) { b0 = bias[gc]; b1 = bias[gc + 1]; }
            float v00 = acc[mt][nt][0] + b0, v01 = acc[mt][nt][1] + b1;
            float v10 = acc[mt][nt][2] + b0, v11 = acc[mt][nt][3] + b1;
            if (RELU) {
                v00 = fmaxf(v00, 0.f); v01 = fmaxf(v01, 0.f);
                v10 = fmaxf(v10, 0.f); v11 = fmaxf(v11, 0.f);
            }
            *(float2*)&C[(size_t)gr * ldc + gc] = make_float2(v00, v01);
            *(float2*)&C[(size_t)(gr + 8) * ldc + gc] = make_float2(v10, v11);
        }
    }
}

// ================= persistent GRU: 768 threads, 2-way K-split (R8-proven, frozen) ==========
#define GRU_SMEM 229376

__device__ __forceinline__ void group_barrier(int g, unsigned* ls) {
    __syncthreads();
    if (threadIdx.x == 0) {
        unsigned s = (*ls) ^ 1u;
        __threadfence();
        unsigned old = atomicAdd(&g_bc[g * 32], 1u);
        if (old == 31u) {
            *(volatile unsigned*)&g_bc[g * 32] = 0u;
            __threadfence();
            g_bs[g * 32] = s;
        } else {
            while (g_bs[g * 32] != s) { }
        }
        __threadfence();
        *ls = s;
    }
    __syncthreads();
}

__global__ void __launch_bounds__(768, 1) gru_persistent(
    const float* __restrict__ xgf, const float* __restrict__ xgb,
    const float* __restrict__ whhf, const float* __restrict__ whhb,
    const float* __restrict__ bhhf, const float* __restrict__ bhhb,
    float* hA, float* hB,
    float* __restrict__ y, float* __restrict__ hid_out)
{
    extern __shared__ float sm[];
    float2* Wsm = (float2*)sm;
    float2* Abuf0 = (float2*)(sm + 49152);
    float2* Abuf1 = (float2*)(sm + 49152 + 4096);
    float*  sg    = sm + 49152;

    int tid = threadIdx.x;
    int lane = tid & 31, warp = tid >> 5;
    int gid = lane >> 2, tig = lane & 3;
    int kh = warp / 12;
    int inner = warp - kh * 12;
    int rw = inner & 3, gw = inner >> 2;

    int bid = blockIdx.x;
    int ct = bid & 31, rt = (bid >> 5) & 1, dir = bid >> 6;
    int grp = bid >> 5;
    const float* Wsrc = dir ? whhb : whhf;
    const float* bhh  = dir ? bhhb : bhhf;
    const float* xg   = dir ? xgb  : xgf;
    const int rowbase = dir * BB + rt * 64;
    const int sxa = gid * 4;

    unsigned ls = g_bs[grp * 32];

    for (int i = tid; i < 48 * 128; i += 768) {
        int lr = i >> 7;
        int q  = i & 127;
        int g = lr >> 4, j = lr & 15;
        float4 v = *(const float4*)(Wsrc + ((size_t)(g * HH + ct * 16 + j)) * HH + q * 4);
        float h0 = cvt_tf32(v.x), h1 = cvt_tf32(v.y), h2 = cvt_tf32(v.z), h3 = cvt_tf32(v.w);
        float l0 = cvt_tf32(v.x - h0), l1 = cvt_tf32(v.y - h1);
        float l2 = cvt_tf32(v.z - h2), l3 = cvt_tf32(v.w - h3);
        int kk = q * 4;
        int w = (kk & ~31) + ((kk & 31) ^ ((lr & 7) * 4));
        float2* row = Wsm + lr * HH;
        *(float4*)&row[w]     = make_float4(h0, l0, h1, l1);
        *(float4*)&row[w + 2] = make_float4(h2, l2, h3, l3);
    }
    __syncthreads();

    for (int t = 0; t < SS; t++) {
        const float* src = (t & 1) ? hB : hA;
        float*       dst = (t & 1) ? hA : hB;
        int tt = dir ? (SS - 1 - t) : t;
        const float* hs = src + (size_t)rowbase * HH;

        float acc[2][4];
        #pragma unroll
        for (int nt = 0; nt < 2; nt++)
            #pragma unroll
            for (int q = 0; q < 4; q++) acc[nt][q] = 0.f;

        for (int L = tid; L < 1024; L += 768) {
            int ch = L >> 9;
            int i = L & 511;
            int r = i >> 3, q = i & 7;
            float4 v = __ldcg((const float4*)(hs + (size_t)r * HH + ch * 32 + q * 4));
            float h0 = cvt_tf32(v.x), h1 = cvt_tf32(v.y), h2 = cvt_tf32(v.z), h3 = cvt_tf32(v.w);
            float l0 = cvt_tf32(v.x - h0), l1 = cvt_tf32(v.y - h1);
            float l2 = cvt_tf32(v.z - h2), l3 = cvt_tf32(v.w - h3);
            int kk = q * 4;
            int w = kk ^ ((r & 7) * 4);
            float2* row = (ch ? Abuf1 : Abuf0) + r * 32;
            *(float4*)&row[w]     = make_float4(h0, l0, h1, l1);
            *(float4*)&row[w + 2] = make_float4(h2, l2, h3, l3);
        }
        __syncthreads();

        const float2* Ab = kh ? Abuf1 : Abuf0;
        const int arow = rw * 16 + gid;

        for (int it = 0; it < 8; it++) {
            bool hasNext = (it + 1 < 8);
            float4 pf0, pf1;
            int r0 = 0, q0 = 0, c0 = 0, r1 = 0, q1 = 0, c1 = 0;
            bool hv1 = false;
            if (hasNext) {
                int base = (it + 1) * 2;
                int L = tid;
                c0 = base + (L >> 9); { int i = L & 511; r0 = i >> 3; q0 = i & 7; }
                pf0 = __ldcg((const float4*)(hs + (size_t)r0 * HH + c0 * 32 + q0 * 4));
                int L2 = tid + 768;
                if (L2 < 1024) {
                    c1 = base + (L2 >> 9); { int i = L2 & 511; r1 = i >> 3; q1 = i & 7; }
                    pf1 = __ldcg((const float4*)(hs + (size_t)r1 * HH + c1 * 32 + q1 * 4));
                    hv1 = true;
                }
            }

            int cc = it * 2 + kh;
            #pragma unroll
            for (int ck = 0; ck < 4; ck++) {
                int k8 = ck * 8;
                float2 a0 = Ab[arow * 32 + ((k8 + tig) ^ sxa)];
                float2 a1 = Ab[(arow + 8) * 32 + ((k8 + tig) ^ sxa)];
                float2 a2 = Ab[arow * 32 + ((k8 + 4 + tig) ^ sxa)];
                float2 a3 = Ab[(arow + 8) * 32 + ((k8 + 4 + tig) ^ sxa)];
                #pragma unroll
                for (int nt = 0; nt < 2; nt++) {
                    int wr = gw * 16 + nt * 8 + gid;
                    const float2* Wb = Wsm + (size_t)wr * HH + cc * 32;
                    float2 b0 = Wb[(k8 + tig) ^ sxa];
                    float2 b1 = Wb[(k8 + 4 + tig) ^ sxa];
                    mma8(acc[nt], FU(a0.x), FU(a1.x), FU(a2.x), FU(a3.x), FU(b0.x), FU(b1.x));
                    mma8(acc[nt], FU(a0.x), FU(a1.x), FU(a2.x), FU(a3.x), FU(b0.y), FU(b1.y));
                    mma8(acc[nt], FU(a0.y), FU(a1.y), FU(a2.y), FU(a3.y), FU(b0.x), FU(b1.x));
                }
            }
            __syncthreads();

            if (hasNext) {
                {
                    float4 v = pf0;
                    float h0 = cvt_tf32(v.x), h1 = cvt_tf32(v.y), h2 = cvt_tf32(v.z), h3 = cvt_tf32(v.w);
                    float l0 = cvt_tf32(v.x - h0), l1 = cvt_tf32(v.y - h1);
                    float l2 = cvt_tf32(v.z - h2), l3 = cvt_tf32(v.w - h3);
                    int kk = q0 * 4;
                    int w = kk ^ ((r0 & 7) * 4);
                    float2* row = ((c0 & 1) ? Abuf1 : Abuf0) + r0 * 32;
                    *(float4*)&row[w]     = make_float4(h0, l0, h1, l1);
                    *(float4*)&row[w + 2] = make_float4(h2, l2, h3, l3);
                }
                if (hv1) {
                    float4 v = pf1;
                    float h0 = cvt_tf32(v.x), h1 = cvt_tf32(v.y), h2 = cvt_tf32(v.z), h3 = cvt_tf32(v.w);
                    float l0 = cvt_tf32(v.x - h0), l1 = cvt_tf32(v.y - h1);
                    float l2 = cvt_tf32(v.z - h2), l3 = cvt_tf32(v.w - h3);
                    int kk = q1 * 4;
                    int w = kk ^ ((r1 & 7) * 4);
                    float2* row = ((c1 & 1) ? Abuf1 : Abuf0) + r1 * 32;
                    *(float4*)&row[w]     = make_float4(h0, l0, h1, l1);
                    *(float4*)&row[w + 2] = make_float4(h2, l2, h3, l3);
                }
                __syncthreads();
            }
        }

        {
            float* sgp = sg + ((size_t)kh * 3 + gw) * 64 * 17;
            #pragma unroll
            for (int nt = 0; nt < 2; nt++) {
                int col = nt * 8 + tig * 2;
                sgp[arow * 17 + col]     = acc[nt][0];
                sgp[arow * 17 + col + 1] = acc[nt][1];
                sgp[(arow + 8) * 17 + col]     = acc[nt][2];
                sgp[(arow + 8) * 17 + col + 1] = acc[nt][3];
            }
        }
        __syncthreads();

        for (int i = tid; i < 1024; i += 768) {
            int row = i >> 4, col = i & 15;
            int bidx = rt * 64 + row;
            int gcol = ct * 16 + col;
            float hr = sg[0 * 64 * 17 + row * 17 + col] + sg[(3 + 0) * 64 * 17 + row * 17 + col] + bhh[gcol];
            float hz = sg[1 * 64 * 17 + row * 17 + col] + sg[(3 + 1) * 64 * 17 + row * 17 + col] + bhh[HH + gcol];
            float hn = sg[2 * 64 * 17 + row * 17 + col] + sg[(3 + 2) * 64 * 17 + row * 17 + col] + bhh[2 * HH + gcol];
            const float* xrow = xg + ((size_t)tt * BB + bidx) * GG;
            float xr = xrow[gcol], xz = xrow[HH + gcol], xn = xrow[2 * HH + gcol];
            float hp = __ldcg(src + (size_t)(rowbase + row) * HH + gcol);
            float rr = 1.f / (1.f + expf(-(xr + hr)));
            float zz = 1.f / (1.f + expf(-(xz + hz)));
            float nn = tanhf(xn + rr * hn);
            float hnew = (1.f - zz) * nn + zz * hp;
            dst[(size_t)(rowbase + row) * HH + gcol] = hnew;
            y[((size_t)tt * BB + bidx) * DD1 + dir * HH + gcol] = hnew;
            if (t == SS - 1)
                hid_out[((size_t)dir * BB + bidx) * HH + gcol] = hnew;
        }

        if (t < SS - 1) group_barrier(grp, &ls);
    }
}

// ---------------- host orchestration ----------------
extern "C" void kernel_launch(void* const* d_in, const int* in_sizes, int n_in,
                              void* d_out, int out_size) {
    const int*   i1    = (const int*)d_in[0];
    const int*   i2    = (const int*)d_in[1];
    const int*   pg    = (const int*)d_in[3];
    const float* emb1  = (const float*)d_in[4];
    const float* emb2  = (const float*)d_in[5];
    const float* wih0f = (const float*)d_in[6];
    const float* whh0f = (const float*)d_in[7];
    const float* bih0f = (const float*)d_in[8];
    const float* bhh0f = (const float*)d_in[9];
    const float* wih0b = (const float*)d_in[10];
    const float* whh0b = (const float*)d_in[11];
    const float* bih0b = (const float*)d_in[12];
    const float* bhh0b = (const float*)d_in[13];
    const float* wih1f = (const float*)d_in[14];
    const float* whh1f = (const float*)d_in[15];
    const float* bih1f = (const float*)d_in[16];
    const float* bhh1f = (const float*)d_in[17];
    const float* wih1b = (const float*)d_in[18];
    const float* whh1b = (const float*)d_in[19];
    const float* bih1b = (const float*)d_in[20];
    const float* bhh1b = (const float*)d_in[21];
    const float* fc1w  = (const float*)d_in[22];
    const float* fc1b  = (const float*)d_in[23];
    const float* fc2w  = (const float*)d_in[24];
    const float* fc2b  = (const float*)d_in[25];
    const float* outw  = (const float*)d_in[26];
    const float* outb  = (const float*)d_in[27];
    float* out = (float*)d_out;

    float *x0, *xgf, *xgb, *y0, *y1, *h0, *h1, *an, *dinv, *node, *node2, *ni, *tmp, *nodeT;
    cudaGetSymbolAddress((void**)&x0,   g_x0);
    cudaGetSymbolAddress((void**)&xgf,  g_xgf);
    cudaGetSymbolAddress((void**)&xgb,  g_xgb);
    cudaGetSymbolAddress((void**)&y0,   g_y0);
    cudaGetSymbolAddress((void**)&y1,   g_y1);
    cudaGetSymbolAddress((void**)&h0,   g_h0);
    cudaGetSymbolAddress((void**)&h1,   g_h1);
    cudaGetSymbolAddress((void**)&an,   g_an);
    cudaGetSymbolAddress((void**)&dinv, g_dinv);
    cudaGetSymbolAddress((void**)&node, g_node);
    cudaGetSymbolAddress((void**)&node2,g_node2);
    cudaGetSymbolAddress((void**)&ni,   g_ni);
    cudaGetSymbolAddress((void**)&tmp,  g_tmp);
    cudaGetSymbolAddress((void**)&nodeT,g_nodeT);

    cudaFuncSetAttribute(gru_persistent,
                         cudaFuncAttributeMaxDynamicSharedMemorySize, GRU_SMEM);

    float* hid_base = out + (size_t)SB * HH;

    // 1) embedding
    embed_kernel<<<(SB * EE + 255) / 256, 256>>>(i1, i2, emb1, emb2, x0);

    // 2) layer0 input gates (fused f+b, N=3072)
    dim3 gG2(2 * GG / 256, SB / 128, 1);
    mma_gemm_nt<false><<<gG2, 256>>>(x0, nullptr, wih0f, wih0b, bih0f, bih0b,
                                     xgf, xgb, EE, 0, GG, EE, EE, GG, 0, 0, 0);

    // 3) layer0 recurrence (persistent)
    cudaMemsetAsync(h0, 0, (size_t)2 * BB * HH * sizeof(float));
    gru_persistent<<<128, 768, GRU_SMEM>>>(xgf, xgb, whh0f, whh0b, bhh0f, bhh0b,
                                           h0, h1, y0, hid_base);

    // 4) layer1 input gates (fused f+b)
    mma_gemm_nt<false><<<gG2, 256>>>(y0, nullptr, wih1f, wih1b, bih1f, bih1b,
                                     xgf, xgb, DD1, 0, GG, DD1, DD1, GG, 0, 0, 0);

    // 5) layer1 recurrence
    cudaMemsetAsync(h0, 0, (size_t)2 * BB * HH * sizeof(float));
    gru_persistent<<<128, 768, GRU_SMEM>>>(xgf, xgb, whh1f, whh1b, bhh1f, bhh1b,
                                           h0, h1, y1, hid_base + 2 * BB * HH);

    // 6) direction sum -> node [B,S,H]
    sumdir_kernel<<<(BB * SS * HH + 255) / 256, 256>>>(y1, node);

    // 7) normalized adjacency
    dinv_kernel<<<BB * SS / 8, 256>>>(pg, dinv);
    an_kernel<<<(BB * SS * SS + 255) / 256, 256>>>(pg, dinv, an);

    // 8) GNN hops
    dim3 gH(HH / 256, SB / 128, 1);
    dim3 gAn(HH / 256, SS / 128, BB);
    dim3 gT(HH / 32, SS / 32, BB);
    float* cur = node; float* nxt = node2;
    for (int i = 0; i < 2; i++) {
        const float* f1w = fc1w + (size_t)i * HH * HH;
        const float* f1b = fc1b + (size_t)i * HH;
        const float* f2w = fc2w + (size_t)i * HH * HH;
        const float* f2b = fc2b + (size_t)i * HH;
        const float* ow  = outw + (size_t)i * HH * DD1;
        const float* ob  = outb + (size_t)i * HH;

        transpose_bsh<<<gT, dim3(32, 8)>>>(cur, nodeT);
        mma_gemm_nt<false><<<gAn, 256>>>(
            an, nullptr, nodeT, nullptr, nullptr, nullptr, tmp, nullptr,
            SS, 0, 0, SS, SS, HH,
            (long long)SS * SS, (long long)HH * SS, (long long)SS * HH);
        mma_gemm_nt<true><<<gH, 256>>>(
            tmp, nullptr, f1w, nullptr, f1b, nullptr, ni, nullptr,
            HH, 0, 0, HH, HH, HH, 0, 0, 0);

        transpose_bsh<<<gT, dim3(32, 8)>>>(ni, nodeT);
        mma_gemm_nt<false><<<gAn, 256>>>(
            an, nullptr, nodeT, nullptr, nullptr, nullptr, tmp, nullptr,
            SS, 0, 0, SS, SS, HH,
            (long long)SS * SS, (long long)HH * SS, (long long)SS * HH);
        mma_gemm_nt<true><<<gH, 256>>>(
            tmp, nullptr, f2w, nullptr, f2b, nullptr, ni, nullptr,
            HH, 0, 0, HH, HH, HH, 0, 0, 0);

        // fused: nxt = relu([cur|ni] @ ow^T + ob), K=1024, split at 512
        mma_gemm_nt<true><<<gH, 256>>>(
            cur, ni, ow, nullptr, ob, nullptr, nxt, nullptr,
            DD1, HH, 0, HH, DD1, HH, 0, 0, 0);
        float* tptr = cur; cur = nxt; nxt = tptr;
    }

    // 9) transpose -> pade_outputs [S,B,H]
    transpose_out_kernel<<<(SS * BB * HH + 255) / 256, 256>>>(cur, out);
}

// round 12
// speedup vs baseline: 1.0566x; 1.0566x over previous
#include <cuda_runtime.h>
#include <math.h>
#include <stdint.h>

#define SS 256
#define BB 128
#define HH 512
#define GG 1536
#define EE 192
#define DD1 1024
#define SB (SS*BB)   // 32768
#define PAD 20       // smem row stride in floats (conflict-free: 20r mod 32 distinct)
#define NSTAGE 3
#define GEMM_SMEM (2 * NSTAGE * 128 * PAD * 4)   // 61440 B

// ---------------- scratch (__device__ globals, no allocation) ----------------
__device__ float g_x0 [SB*EE];
__device__ float g_xgf[SB*GG];
__device__ float g_xgb[SB*GG];
__device__ float g_y0 [SB*DD1];
__device__ float g_y1 [SB*DD1];
__device__ float g_h0 [2*BB*HH];
__device__ float g_h1 [2*BB*HH];
__device__ float g_an [BB*SS*SS];
__device__ float g_dinv[BB*SS];
__device__ float g_node [BB*SS*HH];
__device__ float g_node2[BB*SS*HH];
__device__ float g_ni   [BB*SS*HH];
__device__ float g_tmp  [BB*SS*HH];
__device__ float g_nodeT[BB*HH*SS];

// group-barrier state (4 groups of 32 CTAs; self-consistent across replays)
__device__ unsigned g_bc[128];
__device__ volatile unsigned g_bs[128];

__device__ __forceinline__ float cvt_tf32(float x) {
    uint32_t r;
    asm("cvt.rna.tf32.f32 %0, %1;" : "=r"(r) : "f"(x));
    return __uint_as_float(r);
}

__device__ __forceinline__ uint32_t smem_u32(const void* p) {
    uint32_t a;
    asm("{ .reg .u64 t; cvta.to.shared.u64 t, %1; cvt.u32.u64 %0, t; }" : "=r"(a) : "l"(p));
    return a;
}

__device__ __forceinline__ void cpasync16(uint32_t dst, const void* src) {
    asm volatile("cp.async.cg.shared.global [%0], [%1], 16;" :: "r"(dst), "l"(src));
}
#define CP_COMMIT() asm volatile("cp.async.commit_group;" ::: "memory")
#define CP_WAIT1()  asm volatile("cp.async.wait_group 1;" ::: "memory")

// ---------------- small elementwise kernels ----------------
__global__ void embed_kernel(const int* __restrict__ i1, const int* __restrict__ i2,
                             const float* __restrict__ emb1, const float* __restrict__ emb2,
                             float* __restrict__ x0) {
    int idx = blockIdx.x * blockDim.x + threadIdx.x;
    if (idx >= SB * EE) return;
    int t = idx / EE, e = idx - t * EE;
    if (e < 128) {
        x0[idx] = emb1[(size_t)i1[t] * 128 + e];
    } else {
        int v = i2[t];
        x0[idx] = (v == 0) ? 0.f : emb2[(size_t)v * 64 + (e - 128)];
    }
}

__global__ void dinv_kernel(const int* __restrict__ pg, float* __restrict__ dinv) {
    int row  = blockIdx.x * 8 + (threadIdx.x >> 5);
    int lane = threadIdx.x & 31;
    int b = row >> 8, s = row & 255;
    const int* ar = pg + ((size_t)b * 3 + 2) * (SS * SS) + (size_t)s * SS;
    int acc = 0;
    for (int t = lane; t < SS; t += 32) acc += ar[t];
    #pragma unroll
    for (int o = 16; o; o >>= 1) acc += __shfl_down_sync(0xffffffffu, acc, o);
    if (lane == 0) dinv[row] = rsqrtf((float)acc + 1.0f);
}

__global__ void an_kernel(const int* __restrict__ pg, const float* __restrict__ dinv,
                          float* __restrict__ an) {
    int idx = blockIdx.x * blockDim.x + threadIdx.x;
    if (idx >= BB * SS * SS) return;
    int t = idx & 255, s = (idx >> 8) & 255, b = idx >> 16;
    float a = (float)pg[((size_t)b * 3 + 2) * (SS * SS) + s * SS + t] + (s == t ? 1.f : 0.f);
    an[idx] = a * dinv[b * SS + s] * dinv[b * SS + t];
}

__global__ void sumdir_kernel(const float* __restrict__ y, float* __restrict__ node) {
    int idx = blockIdx.x * blockDim.x + threadIdx.x;
    if (idx >= BB * SS * HH) return;
    int j = idx & 511, s = (idx >> 9) & 255, b = idx >> 17;
    size_t yi = ((size_t)s * BB + b) * DD1 + j;
    node[idx] = y[yi] + y[yi + HH];
}

// [B,S,H] -> [B,H,S]
__global__ void transpose_bsh(const float* __restrict__ src, float* __restrict__ dst) {
    __shared__ float t[32][33];
    int b = blockIdx.z;
    int s0 = blockIdx.y * 32, h0 = blockIdx.x * 32;
    src += (size_t)b * SS * HH;
    dst += (size_t)b * SS * HH;
    int x = threadIdx.x, y = threadIdx.y;
    #pragma unroll
    for (int i = 0; i < 32; i += 8) t[y + i][x] = src[(size_t)(s0 + y + i) * HH + h0 + x];
    __syncthreads();
    #pragma unroll
    for (int i = 0; i < 32; i += 8) dst[(size_t)(h0 + y + i) * SS + s0 + x] = t[x][y + i];
}

// ================= tf32 mma helpers =================
__device__ __forceinline__ void mma8(float* d, uint32_t a0, uint32_t a1, uint32_t a2,
                                     uint32_t a3, uint32_t b0, uint32_t b1) {
    asm volatile(
        "mma.sync.aligned.m16n8k8.row.col.f32.tf32.tf32.f32 "
        "{%0,%1,%2,%3}, {%4,%5,%6,%7}, {%8,%9}, {%0,%1,%2,%3};"
        : "+f"(d[0]), "+f"(d[1]), "+f"(d[2]), "+f"(d[3])
        : "r"(a0), "r"(a1), "r"(a2), "r"(a3), "r"(b0), "r"(b1));
}
#define FU(x) __float_as_uint(x)
#define CV(x) __float_as_uint(cvt_tf32(x))

// ============ tf32 mma.sync NT GEMM — R10 tile (128x128, 64x32 warp) + cp.async pipe ======
// C[m,n] = sum_k A[m,k]*W[n,k] (+bias, +relu).
// A split: k<K1 from A, k>=K1 from A2 (same lda).
// N split: n0>=Nsplit -> W2/bias2/C2, n0-=Nsplit.
// TRANSOUT: write C at [(s*BB+b)*ldc + gc] where gr = b*SS+s (fused final transpose).
// 3-stage cp.async.cg pipeline (L1-bypass); cvt.rna on fragment load (numerics unchanged).
template<bool RELU, bool TRANSOUT>
__global__ void __launch_bounds__(256) mma_gemm_nt(
    const float* __restrict__ A, const float* __restrict__ A2,
    const float* __restrict__ W, const float* __restrict__ W2,
    const float* __restrict__ bias, const float* __restrict__ bias2,
    float* __restrict__ C, float* __restrict__ C2,
    int K, int K1, int Nsplit, int lda, int ldw, int ldc,
    long long sA, long long sW, long long sC)
{
    extern __shared__ float smg[];
    // slots: As[s] at s*2560 floats, Ws[s] at (NSTAGE + s)*2560 floats
    const int SLOT = 128 * PAD;

    int tid = threadIdx.x;
    int lane = tid & 31, warp = tid >> 5;
    int wm = warp >> 2, wn = warp & 3;
    int groupID = lane >> 2, tig = lane & 3;
    int n0 = blockIdx.x * 128, m0 = blockIdx.y * 128;
    if (W2 && n0 >= Nsplit) {
        W = W2; bias = bias2; C = C2; n0 -= Nsplit;
    }
    int z = blockIdx.z;
    A += (size_t)z * (size_t)sA;
    W += (size_t)z * (size_t)sW;
    C += (size_t)z * (size_t)sC;

    int lr = tid >> 2;            // 0..63
    int lc = (tid & 3) * 4;       // 0,4,8,12

    const int arb = wm * 64;
    const int wcb = wn * 32;

    uint32_t smb = smem_u32(smg);
    uint32_t dA0 = smb + (uint32_t)(lr * PAD + lc) * 4u;
    uint32_t dA1 = smb + (uint32_t)((lr + 64) * PAD + lc) * 4u;
    uint32_t dW0 = dA0 + (uint32_t)(NSTAGE * SLOT) * 4u;
    uint32_t dW1 = dA1 + (uint32_t)(NSTAGE * SLOT) * 4u;

    float acc[4][4][4];
    #pragma unroll
    for (int mt = 0; mt < 4; mt++)
        #pragma unroll
        for (int nt = 0; nt < 4; nt++)
            #pragma unroll
            for (int q = 0; q < 4; q++) acc[mt][nt][q] = 0.f;

    auto aload = [&](int c, int s) {
        int koff = c * 16 + lc;
        const float* Ab;
        if (A2 && koff >= K1)
            Ab = A2 + (size_t)(m0 + lr) * lda + (koff - K1);
        else
            Ab = A + (size_t)(m0 + lr) * lda + koff;
        const float* Wb = W + (size_t)(n0 + lr) * ldw + c * 16 + lc;
        uint32_t so = (uint32_t)(s * SLOT) * 4u;
        cpasync16(dA0 + so, Ab);
        cpasync16(dA1 + so, Ab + (size_t)64 * lda);
        cpasync16(dW0 + so, Wb);
        cpasync16(dW1 + so, Wb + (size_t)64 * ldw);
        CP_COMMIT();
    };

    int Cn = K >> 4;
    aload(0, 0);
    aload(1, 1);

    for (int c = 0; c < Cn; c++) {
        CP_WAIT1();
        __syncthreads();

        int slot = c % NSTAGE;
        if (c + 2 < Cn) aload(c + 2, (c + 2) % NSTAGE);

        const float* As = smg + slot * SLOT;
        const float* Ws = smg + (NSTAGE + slot) * SLOT;
        #pragma unroll
        for (int ks = 0; ks < 2; ks++) {
            int k0 = ks * 8;
            float af[4][4], bf[4][2];
            #pragma unroll
            for (int mt = 0; mt < 4; mt++) {
                int rb = arb + mt * 16 + groupID;
                af[mt][0] = As[rb * PAD + k0 + tig];
                af[mt][1] = As[(rb + 8) * PAD + k0 + tig];
                af[mt][2] = As[rb * PAD + k0 + 4 + tig];
                af[mt][3] = As[(rb + 8) * PAD + k0 + 4 + tig];
            }
            #pragma unroll
            for (int nt = 0; nt < 4; nt++) {
                int cb = wcb + nt * 8 + groupID;
                bf[nt][0] = Ws[cb * PAD + k0 + tig];
                bf[nt][1] = Ws[cb * PAD + k0 + 4 + tig];
            }
            uint32_t au[4][4], bu[4][2];
            #pragma unroll
            for (int mt = 0; mt < 4; mt++) {
                au[mt][0] = CV(af[mt][0]); au[mt][1] = CV(af[mt][1]);
                au[mt][2] = CV(af[mt][2]); au[mt][3] = CV(af[mt][3]);
            }
            #pragma unroll
            for (int nt = 0; nt < 4; nt++) {
                bu[nt][0] = CV(bf[nt][0]); bu[nt][1] = CV(bf[nt][1]);
            }
            #pragma unroll
            for (int mt = 0; mt < 4; mt++)
                #pragma unroll
                for (int nt = 0; nt < 4; nt++)
                    mma8(acc[mt][nt], au[mt][0], au[mt][1], au[mt][2], au[mt][3],
                         bu[nt][0], bu[nt][1]);
        }
    }

    #pragma unroll
    for (int mt = 0; mt < 4; mt++) {
        #pragma unroll
        for (int nt = 0; nt < 4; nt++) {
            int gr = m0 + arb + mt * 16 + groupID;
            int gc = n0 + wcb + nt * 8 + tig * 2;
            float b0 = 0.f, b1 = 0.f;
            if (bias) { b0 = bias[gc]; b1 = bias[gc + 1]; }
            float v00 = acc[mt][nt][0] + b0, v01 = acc[mt][nt][1] + b1;
            float v10 = acc[mt][nt][2] + b0, v11 = acc[mt][nt][3] + b1;
            if (RELU) {
                v00 = fmaxf(v00, 0.f); v01 = fmaxf(v01, 0.f);
                v10 = fmaxf(v10, 0.f); v11 = fmaxf(v11, 0.f);
            }
            size_t i0, i1;
            if (TRANSOUT) {
                int b_  = gr >> 8, s_ = gr & 255;
                int b2_ = (gr + 8) >> 8, s2_ = (gr + 8) & 255;
                i0 = ((size_t)s_  * BB + b_ ) * ldc + gc;
                i1 = ((size_t)s2_ * BB + b2_) * ldc + gc;
            } else {
                i0 = (size_t)gr * ldc + gc;
                i1 = (size_t)(gr + 8) * ldc + gc;
            }
            *(float2*)&C[i0] = make_float2(v00, v01);
            *(float2*)&C[i1] = make_float2(v10, v11);
        }
    }
}

// ================= persistent GRU: 768 threads, 2-way K-split (R8-proven, frozen) ==========
#define GRU_SMEM 229376

__device__ __forceinline__ void group_barrier(int g, unsigned* ls) {
    __syncthreads();
    if (threadIdx.x == 0) {
        unsigned s = (*ls) ^ 1u;
        __threadfence();
        unsigned old = atomicAdd(&g_bc[g * 32], 1u);
        if (old == 31u) {
            *(volatile unsigned*)&g_bc[g * 32] = 0u;
            __threadfence();
            g_bs[g * 32] = s;
        } else {
            while (g_bs[g * 32] != s) { }
        }
        __threadfence();
        *ls = s;
    }
    __syncthreads();
}

__global__ void __launch_bounds__(768, 1) gru_persistent(
    const float* __restrict__ xgf, const float* __restrict__ xgb,
    const float* __restrict__ whhf, const float* __restrict__ whhb,
    const float* __restrict__ bhhf, const float* __restrict__ bhhb,
    float* hA, float* hB,
    float* __restrict__ y, float* __restrict__ hid_out)
{
    extern __shared__ float sm[];
    float2* Wsm = (float2*)sm;
    float2* Abuf0 = (float2*)(sm + 49152);
    float2* Abuf1 = (float2*)(sm + 49152 + 4096);
    float*  sg    = sm + 49152;

    int tid = threadIdx.x;
    int lane = tid & 31, warp = tid >> 5;
    int gid = lane >> 2, tig = lane & 3;
    int kh = warp / 12;
    int inner = warp - kh * 12;
    int rw = inner & 3, gw = inner >> 2;

    int bid = blockIdx.x;
    int ct = bid & 31, rt = (bid >> 5) & 1, dir = bid >> 6;
    int grp = bid >> 5;
    const float* Wsrc = dir ? whhb : whhf;
    const float* bhh  = dir ? bhhb : bhhf;
    const float* xg   = dir ? xgb  : xgf;
    const int rowbase = dir * BB + rt * 64;
    const int sxa = gid * 4;

    unsigned ls = g_bs[grp * 32];

    for (int i = tid; i < 48 * 128; i += 768) {
        int lr = i >> 7;
        int q  = i & 127;
        int g = lr >> 4, j = lr & 15;
        float4 v = *(const float4*)(Wsrc + ((size_t)(g * HH + ct * 16 + j)) * HH + q * 4);
        float h0 = cvt_tf32(v.x), h1 = cvt_tf32(v.y), h2 = cvt_tf32(v.z), h3 = cvt_tf32(v.w);
        float l0 = cvt_tf32(v.x - h0), l1 = cvt_tf32(v.y - h1);
        float l2 = cvt_tf32(v.z - h2), l3 = cvt_tf32(v.w - h3);
        int kk = q * 4;
        int w = (kk & ~31) + ((kk & 31) ^ ((lr & 7) * 4));
        float2* row = Wsm + lr * HH;
        *(float4*)&row[w]     = make_float4(h0, l0, h1, l1);
        *(float4*)&row[w + 2] = make_float4(h2, l2, h3, l3);
    }
    __syncthreads();

    for (int t = 0; t < SS; t++) {
        const float* src = (t & 1) ? hB : hA;
        float*       dst = (t & 1) ? hA : hB;
        int tt = dir ? (SS - 1 - t) : t;
        const float* hs = src + (size_t)rowbase * HH;

        float acc[2][4];
        #pragma unroll
        for (int nt = 0; nt < 2; nt++)
            #pragma unroll
            for (int q = 0; q < 4; q++) acc[nt][q] = 0.f;

        for (int L = tid; L < 1024; L += 768) {
            int ch = L >> 9;
            int i = L & 511;
            int r = i >> 3, q = i & 7;
            float4 v = __ldcg((const float4*)(hs + (size_t)r * HH + ch * 32 + q * 4));
            float h0 = cvt_tf32(v.x), h1 = cvt_tf32(v.y), h2 = cvt_tf32(v.z), h3 = cvt_tf32(v.w);
            float l0 = cvt_tf32(v.x - h0), l1 = cvt_tf32(v.y - h1);
            float l2 = cvt_tf32(v.z - h2), l3 = cvt_tf32(v.w - h3);
            int kk = q * 4;
            int w = kk ^ ((r & 7) * 4);
            float2* row = (ch ? Abuf1 : Abuf0) + r * 32;
            *(float4*)&row[w]     = make_float4(h0, l0, h1, l1);
            *(float4*)&row[w + 2] = make_float4(h2, l2, h3, l3);
        }
        __syncthreads();

        const float2* Ab = kh ? Abuf1 : Abuf0;
        const int arow = rw * 16 + gid;

        for (int it = 0; it < 8; it++) {
            bool hasNext = (it + 1 < 8);
            float4 pf0, pf1;
            int r0 = 0, q0 = 0, c0 = 0, r1 = 0, q1 = 0, c1 = 0;
            bool hv1 = false;
            if (hasNext) {
                int base = (it + 1) * 2;
                int L = tid;
                c0 = base + (L >> 9); { int i = L & 511; r0 = i >> 3; q0 = i & 7; }
                pf0 = __ldcg((const float4*)(hs + (size_t)r0 * HH + c0 * 32 + q0 * 4));
                int L2 = tid + 768;
                if (L2 < 1024) {
                    c1 = base + (L2 >> 9); { int i = L2 & 511; r1 = i >> 3; q1 = i & 7; }
                    pf1 = __ldcg((const float4*)(hs + (size_t)r1 * HH + c1 * 32 + q1 * 4));
                    hv1 = true;
                }
            }

            int cc = it * 2 + kh;
            #pragma unroll
            for (int ck = 0; ck < 4; ck++) {
                int k8 = ck * 8;
                float2 a0 = Ab[arow * 32 + ((k8 + tig) ^ sxa)];
                float2 a1 = Ab[(arow + 8) * 32 + ((k8 + tig) ^ sxa)];
                float2 a2 = Ab[arow * 32 + ((k8 + 4 + tig) ^ sxa)];
                float2 a3 = Ab[(arow + 8) * 32 + ((k8 + 4 + tig) ^ sxa)];
                #pragma unroll
                for (int nt = 0; nt < 2; nt++) {
                    int wr = gw * 16 + nt * 8 + gid;
                    const float2* Wb = Wsm + (size_t)wr * HH + cc * 32;
                    float2 b0 = Wb[(k8 + tig) ^ sxa];
                    float2 b1 = Wb[(k8 + 4 + tig) ^ sxa];
                    mma8(acc[nt], FU(a0.x), FU(a1.x), FU(a2.x), FU(a3.x), FU(b0.x), FU(b1.x));
                    mma8(acc[nt], FU(a0.x), FU(a1.x), FU(a2.x), FU(a3.x), FU(b0.y), FU(b1.y));
                    mma8(acc[nt], FU(a0.y), FU(a1.y), FU(a2.y), FU(a3.y), FU(b0.x), FU(b1.x));
                }
            }
            __syncthreads();

            if (hasNext) {
                {
                    float4 v = pf0;
                    float h0 = cvt_tf32(v.x), h1 = cvt_tf32(v.y), h2 = cvt_tf32(v.z), h3 = cvt_tf32(v.w);
                    float l0 = cvt_tf32(v.x - h0), l1 = cvt_tf32(v.y - h1);
                    float l2 = cvt_tf32(v.z - h2), l3 = cvt_tf32(v.w - h3);
                    int kk = q0 * 4;
                    int w = kk ^ ((r0 & 7) * 4);
                    float2* row = ((c0 & 1) ? Abuf1 : Abuf0) + r0 * 32;
                    *(float4*)&row[w]     = make_float4(h0, l0, h1, l1);
                    *(float4*)&row[w + 2] = make_float4(h2, l2, h3, l3);
                }
                if (hv1) {
                    float4 v = pf1;
                    float h0 = cvt_tf32(v.x), h1 = cvt_tf32(v.y), h2 = cvt_tf32(v.z), h3 = cvt_tf32(v.w);
                    float l0 = cvt_tf32(v.x - h0), l1 = cvt_tf32(v.y - h1);
                    float l2 = cvt_tf32(v.z - h2), l3 = cvt_tf32(v.w - h3);
                    int kk = q1 * 4;
                    int w = kk ^ ((r1 & 7) * 4);
                    float2* row = ((c1 & 1) ? Abuf1 : Abuf0) + r1 * 32;
                    *(float4*)&row[w]     = make_float4(h0, l0, h1, l1);
                    *(float4*)&row[w + 2] = make_float4(h2, l2, h3, l3);
                }
                __syncthreads();
            }
        }

        {
            float* sgp = sg + ((size_t)kh * 3 + gw) * 64 * 17;
            #pragma unroll
            for (int nt = 0; nt < 2; nt++) {
                int col = nt * 8 + tig * 2;
                sgp[arow * 17 + col]     = acc[nt][0];
                sgp[arow * 17 + col + 1] = acc[nt][1];
                sgp[(arow + 8) * 17 + col]     = acc[nt][2];
                sgp[(arow + 8) * 17 + col + 1] = acc[nt][3];
            }
        }
        __syncthreads();

        for (int i = tid; i < 1024; i += 768) {
            int row = i >> 4, col = i & 15;
            int bidx = rt * 64 + row;
            int gcol = ct * 16 + col;
            float hr = sg[0 * 64 * 17 + row * 17 + col] + sg[(3 + 0) * 64 * 17 + row * 17 + col] + bhh[gcol];
            float hz = sg[1 * 64 * 17 + row * 17 + col] + sg[(3 + 1) * 64 * 17 + row * 17 + col] + bhh[HH + gcol];
            float hn = sg[2 * 64 * 17 + row * 17 + col] + sg[(3 + 2) * 64 * 17 + row * 17 + col] + bhh[2 * HH + gcol];
            const float* xrow = xg + ((size_t)tt * BB + bidx) * GG;
            float xr = xrow[gcol], xz = xrow[HH + gcol], xn = xrow[2 * HH + gcol];
            float hp = __ldcg(src + (size_t)(rowbase + row) * HH + gcol);
            float rr = 1.f / (1.f + expf(-(xr + hr)));
            float zz = 1.f / (1.f + expf(-(xz + hz)));
            float nn = tanhf(xn + rr * hn);
            float hnew = (1.f - zz) * nn + zz * hp;
            dst[(size_t)(rowbase + row) * HH + gcol] = hnew;
            y[((size_t)tt * BB + bidx) * DD1 + dir * HH + gcol] = hnew;
            if (t == SS - 1)
                hid_out[((size_t)dir * BB + bidx) * HH + gcol] = hnew;
        }

        if (t < SS - 1) group_barrier(grp, &ls);
    }
}

// ---------------- host orchestration ----------------
extern "C" void kernel_launch(void* const* d_in, const int* in_sizes, int n_in,
                              void* d_out, int out_size) {
    const int*   i1    = (const int*)d_in[0];
    const int*   i2    = (const int*)d_in[1];
    const int*   pg    = (const int*)d_in[3];
    const float* emb1  = (const float*)d_in[4];
    const float* emb2  = (const float*)d_in[5];
    const float* wih0f = (const float*)d_in[6];
    const float* whh0f = (const float*)d_in[7];
    const float* bih0f = (const float*)d_in[8];
    const float* bhh0f = (const float*)d_in[9];
    const float* wih0b = (const float*)d_in[10];
    const float* whh0b = (const float*)d_in[11];
    const float* bih0b = (const float*)d_in[12];
    const float* bhh0b = (const float*)d_in[13];
    const float* wih1f = (const float*)d_in[14];
    const float* whh1f = (const float*)d_in[15];
    const float* bih1f = (const float*)d_in[16];
    const float* bhh1f = (const float*)d_in[17];
    const float* wih1b = (const float*)d_in[18];
    const float* whh1b = (const float*)d_in[19];
    const float* bih1b = (const float*)d_in[20];
    const float* bhh1b = (const float*)d_in[21];
    const float* fc1w  = (const float*)d_in[22];
    const float* fc1b  = (const float*)d_in[23];
    const float* fc2w  = (const float*)d_in[24];
    const float* fc2b  = (const float*)d_in[25];
    const float* outw  = (const float*)d_in[26];
    const float* outb  = (const float*)d_in[27];
    float* out = (float*)d_out;

    float *x0, *xgf, *xgb, *y0, *y1, *h0, *h1, *an, *dinv, *node, *node2, *ni, *tmp, *nodeT;
    cudaGetSymbolAddress((void**)&x0,   g_x0);
    cudaGetSymbolAddress((void**)&xgf,  g_xgf);
    cudaGetSymbolAddress((void**)&xgb,  g_xgb);
    cudaGetSymbolAddress((void**)&y0,   g_y0);
    cudaGetSymbolAddress((void**)&y1,   g_y1);
    cudaGetSymbolAddress((void**)&h0,   g_h0);
    cudaGetSymbolAddress((void**)&h1,   g_h1);
    cudaGetSymbolAddress((void**)&an,   g_an);
    cudaGetSymbolAddress((void**)&dinv, g_dinv);
    cudaGetSymbolAddress((void**)&node, g_node);
    cudaGetSymbolAddress((void**)&node2,g_node2);
    cudaGetSymbolAddress((void**)&ni,   g_ni);
    cudaGetSymbolAddress((void**)&tmp,  g_tmp);
    cudaGetSymbolAddress((void**)&nodeT,g_nodeT);

    cudaFuncSetAttribute(gru_persistent,
                         cudaFuncAttributeMaxDynamicSharedMemorySize, GRU_SMEM);
    cudaFuncSetAttribute(mma_gemm_nt<false,false>,
                         cudaFuncAttributeMaxDynamicSharedMemorySize, GEMM_SMEM);
    cudaFuncSetAttribute(mma_gemm_nt<true,false>,
                         cudaFuncAttributeMaxDynamicSharedMemorySize, GEMM_SMEM);
    cudaFuncSetAttribute(mma_gemm_nt<true,true>,
                         cudaFuncAttributeMaxDynamicSharedMemorySize, GEMM_SMEM);

    float* hid_base = out + (size_t)SB * HH;

    // 1) embedding
    embed_kernel<<<(SB * EE + 255) / 256, 256>>>(i1, i2, emb1, emb2, x0);

    // 2) layer0 input gates (fused f+b, N=3072)
    dim3 gG2(2 * GG / 128, SB / 128, 1);
    mma_gemm_nt<false,false><<<gG2, 256, GEMM_SMEM>>>(
        x0, nullptr, wih0f, wih0b, bih0f, bih0b,
        xgf, xgb, EE, 0, GG, EE, EE, GG, 0, 0, 0);

    // 3) layer0 recurrence (persistent)
    cudaMemsetAsync(h0, 0, (size_t)2 * BB * HH * sizeof(float));
    gru_persistent<<<128, 768, GRU_SMEM>>>(xgf, xgb, whh0f, whh0b, bhh0f, bhh0b,
                                           h0, h1, y0, hid_base);

    // 4) layer1 input gates (fused f+b)
    mma_gemm_nt<false,false><<<gG2, 256, GEMM_SMEM>>>(
        y0, nullptr, wih1f, wih1b, bih1f, bih1b,
        xgf, xgb, DD1, 0, GG, DD1, DD1, GG, 0, 0, 0);

    // 5) layer1 recurrence
    cudaMemsetAsync(h0, 0, (size_t)2 * BB * HH * sizeof(float));
    gru_persistent<<<128, 768, GRU_SMEM>>>(xgf, xgb, whh1f, whh1b, bhh1f, bhh1b,
                                           h0, h1, y1, hid_base + 2 * BB * HH);

    // 6) direction sum -> node [B,S,H]
    sumdir_kernel<<<(BB * SS * HH + 255) / 256, 256>>>(y1, node);

    // 7) normalized adjacency
    dinv_kernel<<<BB * SS / 8, 256>>>(pg, dinv);
    an_kernel<<<(BB * SS * SS + 255) / 256, 256>>>(pg, dinv, an);

    // 8) GNN hops
    dim3 gH(HH / 128, SB / 128, 1);
    dim3 gAn(HH / 128, SS / 128, BB);
    dim3 gT(HH / 32, SS / 32, BB);
    float* cur = node; float* nxt = node2;
    for (int i = 0; i < 2; i++) {
        const float* f1w = fc1w + (size_t)i * HH * HH;
        const float* f1b = fc1b + (size_t)i * HH;
        const float* f2w = fc2w + (size_t)i * HH * HH;
        const float* f2b = fc2b + (size_t)i * HH;
        const float* ow  = outw + (size_t)i * HH * DD1;
        const float* ob  = outb + (size_t)i * HH;

        transpose_bsh<<<gT, dim3(32, 8)>>>(cur, nodeT);
        mma_gemm_nt<false,false><<<gAn, 256, GEMM_SMEM>>>(
            an, nullptr, nodeT, nullptr, nullptr, nullptr, tmp, nullptr,
            SS, 0, 0, SS, SS, HH,
            (long long)SS * SS, (long long)HH * SS, (long long)SS * HH);
        mma_gemm_nt<true,false><<<gH, 256, GEMM_SMEM>>>(
            tmp, nullptr, f1w, nullptr, f1b, nullptr, ni, nullptr,
            HH, 0, 0, HH, HH, HH, 0, 0, 0);

        transpose_bsh<<<gT, dim3(32, 8)>>>(ni, nodeT);
        mma_gemm_nt<false,false><<<gAn, 256, GEMM_SMEM>>>(
            an, nullptr, nodeT, nullptr, nullptr, nullptr, tmp, nullptr,
            SS, 0, 0, SS, SS, HH,
            (long long)SS * SS, (long long)HH * SS, (long long)SS * HH);
        mma_gemm_nt<true,false><<<gH, 256, GEMM_SMEM>>>(
            tmp, nullptr, f2w, nullptr, f2b, nullptr, ni, nullptr,
            HH, 0, 0, HH, HH, HH, 0, 0, 0);

        // fused: out = relu([cur|ni] @ ow^T + ob), K=1024, split at 512
        if (i == 0) {
            mma_gemm_nt<true,false><<<gH, 256, GEMM_SMEM>>>(
                cur, ni, ow, nullptr, ob, nullptr, nxt, nullptr,
                DD1, HH, 0, HH, DD1, HH, 0, 0, 0);
            float* tptr = cur; cur = nxt; nxt = tptr;
        } else {
            // final hop: write pade_outputs [S,B,H] directly (fused transpose)
            mma_gemm_nt<true,true><<<gH, 256, GEMM_SMEM>>>(
                cur, ni, ow, nullptr, ob, nullptr, out, nullptr,
                DD1, HH, 0, HH, DD1, HH, 0, 0, 0);
        }
    }
}

// round 13
// speedup vs baseline: 1.1536x; 1.0918x over previous
#include <cuda_runtime.h>
#include <math.h>
#include <stdint.h>

#define SS 256
#define BB 128
#define HH 512
#define GG 1536
#define EE 192
#define DD1 1024
#define SB (SS*BB)   // 32768
#define PAD 20       // smem row stride in floats (conflict-free: 20r mod 32 distinct)
#define NSTAGE 3
#define GEMM_SMEM (2 * NSTAGE * 128 * PAD * 4)   // 61440 B

// ---------------- scratch (__device__ globals, no allocation) ----------------
__device__ float g_x0 [SB*EE];
__device__ float g_xgf[SB*GG];
__device__ float g_xgb[SB*GG];
__device__ float g_y0 [SB*DD1];
__device__ float g_y1 [SB*DD1];
__device__ float g_h0 [2*BB*HH];
__device__ float g_h1 [2*BB*HH];
__device__ float g_an [BB*SS*SS];
__device__ float g_dinv[BB*SS];
__device__ float g_node [BB*SS*HH];
__device__ float g_node2[BB*SS*HH];
__device__ float g_ni   [BB*SS*HH];
__device__ float g_tmp  [BB*SS*HH];
__device__ float g_nodeT[BB*HH*SS];

// group-barrier state (4 groups of 32 CTAs; self-consistent across replays)
__device__ unsigned g_bc[128];
__device__ volatile unsigned g_bs[128];

__device__ __forceinline__ float cvt_tf32(float x) {
    uint32_t r;
    asm("cvt.rna.tf32.f32 %0, %1;" : "=r"(r) : "f"(x));
    return __uint_as_float(r);
}

__device__ __forceinline__ uint32_t smem_u32(const void* p) {
    uint32_t a;
    asm("{ .reg .u64 t; cvta.to.shared.u64 t, %1; cvt.u32.u64 %0, t; }" : "=r"(a) : "l"(p));
    return a;
}

__device__ __forceinline__ void cpasync16(uint32_t dst, const void* src) {
    asm volatile("cp.async.cg.shared.global [%0], [%1], 16;" :: "r"(dst), "l"(src));
}
#define CP_COMMIT() asm volatile("cp.async.commit_group;" ::: "memory")
#define CP_WAIT1()  asm volatile("cp.async.wait_group 1;" ::: "memory")

// ---------------- small elementwise kernels ----------------
__global__ void embed_kernel(const int* __restrict__ i1, const int* __restrict__ i2,
                             const float* __restrict__ emb1, const float* __restrict__ emb2,
                             float* __restrict__ x0) {
    int idx = blockIdx.x * blockDim.x + threadIdx.x;
    if (idx >= SB * EE) return;
    int t = idx / EE, e = idx - t * EE;
    if (e < 128) {
        x0[idx] = emb1[(size_t)i1[t] * 128 + e];
    } else {
        int v = i2[t];
        x0[idx] = (v == 0) ? 0.f : emb2[(size_t)v * 64 + (e - 128)];
    }
}

__global__ void dinv_kernel(const int* __restrict__ pg, float* __restrict__ dinv) {
    int row  = blockIdx.x * 8 + (threadIdx.x >> 5);
    int lane = threadIdx.x & 31;
    int b = row >> 8, s = row & 255;
    const int* ar = pg + ((size_t)b * 3 + 2) * (SS * SS) + (size_t)s * SS;
    int acc = 0;
    for (int t = lane; t < SS; t += 32) acc += ar[t];
    #pragma unroll
    for (int o = 16; o; o >>= 1) acc += __shfl_down_sync(0xffffffffu, acc, o);
    if (lane == 0) dinv[row] = rsqrtf((float)acc + 1.0f);
}

__global__ void an_kernel(const int* __restrict__ pg, const float* __restrict__ dinv,
                          float* __restrict__ an) {
    int idx = blockIdx.x * blockDim.x + threadIdx.x;
    if (idx >= BB * SS * SS) return;
    int t = idx & 255, s = (idx >> 8) & 255, b = idx >> 16;
    float a = (float)pg[((size_t)b * 3 + 2) * (SS * SS) + s * SS + t] + (s == t ? 1.f : 0.f);
    an[idx] = a * dinv[b * SS + s] * dinv[b * SS + t];
}

__global__ void sumdir_kernel(const float* __restrict__ y, float* __restrict__ node) {
    int idx = blockIdx.x * blockDim.x + threadIdx.x;
    if (idx >= BB * SS * HH) return;
    int j = idx & 511, s = (idx >> 9) & 255, b = idx >> 17;
    size_t yi = ((size_t)s * BB + b) * DD1 + j;
    node[idx] = y[yi] + y[yi + HH];
}

// [B,S,H] -> [B,H,S]
__global__ void transpose_bsh(const float* __restrict__ src, float* __restrict__ dst) {
    __shared__ float t[32][33];
    int b = blockIdx.z;
    int s0 = blockIdx.y * 32, h0 = blockIdx.x * 32;
    src += (size_t)b * SS * HH;
    dst += (size_t)b * SS * HH;
    int x = threadIdx.x, y = threadIdx.y;
    #pragma unroll
    for (int i = 0; i < 32; i += 8) t[y + i][x] = src[(size_t)(s0 + y + i) * HH + h0 + x];
    __syncthreads();
    #pragma unroll
    for (int i = 0; i < 32; i += 8) dst[(size_t)(h0 + y + i) * SS + s0 + x] = t[x][y + i];
}

// ================= tf32 mma helpers =================
__device__ __forceinline__ void mma8(float* d, uint32_t a0, uint32_t a1, uint32_t a2,
                                     uint32_t a3, uint32_t b0, uint32_t b1) {
    asm volatile(
        "mma.sync.aligned.m16n8k8.row.col.f32.tf32.tf32.f32 "
        "{%0,%1,%2,%3}, {%4,%5,%6,%7}, {%8,%9}, {%0,%1,%2,%3};"
        : "+f"(d[0]), "+f"(d[1]), "+f"(d[2]), "+f"(d[3])
        : "r"(a0), "r"(a1), "r"(a2), "r"(a3), "r"(b0), "r"(b1));
}
#define FU(x) __float_as_uint(x)
#define CV(x) __float_as_uint(cvt_tf32(x))

// ============ tf32 mma.sync NT GEMM — R12-proven (cp.async pipe, fused transpose) ========
template<bool RELU, bool TRANSOUT>
__global__ void __launch_bounds__(256) mma_gemm_nt(
    const float* __restrict__ A, const float* __restrict__ A2,
    const float* __restrict__ W, const float* __restrict__ W2,
    const float* __restrict__ bias, const float* __restrict__ bias2,
    float* __restrict__ C, float* __restrict__ C2,
    int K, int K1, int Nsplit, int lda, int ldw, int ldc,
    long long sA, long long sW, long long sC)
{
    extern __shared__ float smg[];
    const int SLOT = 128 * PAD;

    int tid = threadIdx.x;
    int lane = tid & 31, warp = tid >> 5;
    int wm = warp >> 2, wn = warp & 3;
    int groupID = lane >> 2, tig = lane & 3;
    int n0 = blockIdx.x * 128, m0 = blockIdx.y * 128;
    if (W2 && n0 >= Nsplit) {
        W = W2; bias = bias2; C = C2; n0 -= Nsplit;
    }
    int z = blockIdx.z;
    A += (size_t)z * (size_t)sA;
    W += (size_t)z * (size_t)sW;
    C += (size_t)z * (size_t)sC;

    int lr = tid >> 2;
    int lc = (tid & 3) * 4;

    const int arb = wm * 64;
    const int wcb = wn * 32;

    uint32_t smb = smem_u32(smg);
    uint32_t dA0 = smb + (uint32_t)(lr * PAD + lc) * 4u;
    uint32_t dA1 = smb + (uint32_t)((lr + 64) * PAD + lc) * 4u;
    uint32_t dW0 = dA0 + (uint32_t)(NSTAGE * SLOT) * 4u;
    uint32_t dW1 = dA1 + (uint32_t)(NSTAGE * SLOT) * 4u;

    float acc[4][4][4];
    #pragma unroll
    for (int mt = 0; mt < 4; mt++)
        #pragma unroll
        for (int nt = 0; nt < 4; nt++)
            #pragma unroll
            for (int q = 0; q < 4; q++) acc[mt][nt][q] = 0.f;

    auto aload = [&](int c, int s) {
        int koff = c * 16 + lc;
        const float* Ab;
        if (A2 && koff >= K1)
            Ab = A2 + (size_t)(m0 + lr) * lda + (koff - K1);
        else
            Ab = A + (size_t)(m0 + lr) * lda + koff;
        const float* Wb = W + (size_t)(n0 + lr) * ldw + c * 16 + lc;
        uint32_t so = (uint32_t)(s * SLOT) * 4u;
        cpasync16(dA0 + so, Ab);
        cpasync16(dA1 + so, Ab + (size_t)64 * lda);
        cpasync16(dW0 + so, Wb);
        cpasync16(dW1 + so, Wb + (size_t)64 * ldw);
        CP_COMMIT();
    };

    int Cn = K >> 4;
    aload(0, 0);
    aload(1, 1);

    for (int c = 0; c < Cn; c++) {
        CP_WAIT1();
        __syncthreads();

        int slot = c % NSTAGE;
        if (c + 2 < Cn) aload(c + 2, (c + 2) % NSTAGE);

        const float* As = smg + slot * SLOT;
        const float* Ws = smg + (NSTAGE + slot) * SLOT;
        #pragma unroll
        for (int ks = 0; ks < 2; ks++) {
            int k0 = ks * 8;
            float af[4][4], bf[4][2];
            #pragma unroll
            for (int mt = 0; mt < 4; mt++) {
                int rb = arb + mt * 16 + groupID;
                af[mt][0] = As[rb * PAD + k0 + tig];
                af[mt][1] = As[(rb + 8) * PAD + k0 + tig];
                af[mt][2] = As[rb * PAD + k0 + 4 + tig];
                af[mt][3] = As[(rb + 8) * PAD + k0 + 4 + tig];
            }
            #pragma unroll
            for (int nt = 0; nt < 4; nt++) {
                int cb = wcb + nt * 8 + groupID;
                bf[nt][0] = Ws[cb * PAD + k0 + tig];
                bf[nt][1] = Ws[cb * PAD + k0 + 4 + tig];
            }
            uint32_t au[4][4], bu[4][2];
            #pragma unroll
            for (int mt = 0; mt < 4; mt++) {
                au[mt][0] = CV(af[mt][0]); au[mt][1] = CV(af[mt][1]);
                au[mt][2] = CV(af[mt][2]); au[mt][3] = CV(af[mt][3]);
            }
            #pragma unroll
            for (int nt = 0; nt < 4; nt++) {
                bu[nt][0] = CV(bf[nt][0]); bu[nt][1] = CV(bf[nt][1]);
            }
            #pragma unroll
            for (int mt = 0; mt < 4; mt++)
                #pragma unroll
                for (int nt = 0; nt < 4; nt++)
                    mma8(acc[mt][nt], au[mt][0], au[mt][1], au[mt][2], au[mt][3],
                         bu[nt][0], bu[nt][1]);
        }
    }

    #pragma unroll
    for (int mt = 0; mt < 4; mt++) {
        #pragma unroll
        for (int nt = 0; nt < 4; nt++) {
            int gr = m0 + arb + mt * 16 + groupID;
            int gc = n0 + wcb + nt * 8 + tig * 2;
            float b0 = 0.f, b1 = 0.f;
            if (bias) { b0 = bias[gc]; b1 = bias[gc + 1]; }
            float v00 = acc[mt][nt][0] + b0, v01 = acc[mt][nt][1] + b1;
            float v10 = acc[mt][nt][2] + b0, v11 = acc[mt][nt][3] + b1;
            if (RELU) {
                v00 = fmaxf(v00, 0.f); v01 = fmaxf(v01, 0.f);
                v10 = fmaxf(v10, 0.f); v11 = fmaxf(v11, 0.f);
            }
            size_t i0, i1;
            if (TRANSOUT) {
                int b_  = gr >> 8, s_ = gr & 255;
                int b2_ = (gr + 8) >> 8, s2_ = (gr + 8) & 255;
                i0 = ((size_t)s_  * BB + b_ ) * ldc + gc;
                i1 = ((size_t)s2_ * BB + b2_) * ldc + gc;
            } else {
                i0 = (size_t)gr * ldc + gc;
                i1 = (size_t)(gr + 8) * ldc + gc;
            }
            *(float2*)&C[i0] = make_float2(v00, v01);
            *(float2*)&C[i1] = make_float2(v10, v11);
        }
    }
}

// ================= persistent GRU: 2-term split (tf32 W, hi/lo h) =================
// hg = hi@Whi + lo@Whi = h@Whi (weights tf32-rounded, h fp32-accurate).
// Wsm: [48][512] float (hi only, swizzled) = 98304 B; A bufs 2x float2[64][32] = 32768 B.
#define GRU_SMEM 131072

__device__ __forceinline__ void group_barrier(int g, unsigned* ls) {
    __syncthreads();
    if (threadIdx.x == 0) {
        unsigned s = (*ls) ^ 1u;
        __threadfence();
        unsigned old = atomicAdd(&g_bc[g * 32], 1u);
        if (old == 31u) {
            *(volatile unsigned*)&g_bc[g * 32] = 0u;
            __threadfence();
            g_bs[g * 32] = s;
        } else {
            while (g_bs[g * 32] != s) { }
        }
        __threadfence();
        *ls = s;
    }
    __syncthreads();
}

__global__ void __launch_bounds__(768, 1) gru_persistent(
    const float* __restrict__ xgf, const float* __restrict__ xgb,
    const float* __restrict__ whhf, const float* __restrict__ whhb,
    const float* __restrict__ bhhf, const float* __restrict__ bhhb,
    float* hA, float* hB,
    float* __restrict__ y, float* __restrict__ hid_out)
{
    extern __shared__ float sm[];
    float*  Wsm   = sm;                               // [48][512] hi, swizzled
    float2* Abuf0 = (float2*)(sm + 24576);            // [64][32] hi/lo
    float2* Abuf1 = (float2*)(sm + 24576 + 4096);
    float*  sg    = sm + 24576;                       // epilogue overlay [2][3][64][17]

    int tid = threadIdx.x;
    int lane = tid & 31, warp = tid >> 5;
    int gid = lane >> 2, tig = lane & 3;
    int kh = warp / 12;
    int inner = warp - kh * 12;
    int rw = inner & 3, gw = inner >> 2;

    int bid = blockIdx.x;
    int ct = bid & 31, rt = (bid >> 5) & 1, dir = bid >> 6;
    int grp = bid >> 5;
    const float* Wsrc = dir ? whhb : whhf;
    const float* bhh  = dir ? bhhb : bhhf;
    const float* xg   = dir ? xgb  : xgf;
    const int rowbase = dir * BB + rt * 64;
    const int sxa = gid * 4;

    unsigned ls = g_bs[grp * 32];

    // preload weights (tf32 hi only), swizzled
    for (int i = tid; i < 48 * 128; i += 768) {
        int lr = i >> 7;
        int q  = i & 127;
        int g = lr >> 4, j = lr & 15;
        float4 v = *(const float4*)(Wsrc + ((size_t)(g * HH + ct * 16 + j)) * HH + q * 4);
        int kk = q * 4;
        int w = (kk & ~31) + ((kk & 31) ^ ((lr & 7) * 4));
        *(float4*)&Wsm[lr * HH + w] =
            make_float4(cvt_tf32(v.x), cvt_tf32(v.y), cvt_tf32(v.z), cvt_tf32(v.w));
    }
    __syncthreads();

    for (int t = 0; t < SS; t++) {
        const float* src = (t & 1) ? hB : hA;
        float*       dst = (t & 1) ? hA : hB;
        int tt = dir ? (SS - 1 - t) : t;
        const float* hs = src + (size_t)rowbase * HH;

        float acc[2][4];
        #pragma unroll
        for (int nt = 0; nt < 2; nt++)
            #pragma unroll
            for (int q = 0; q < 4; q++) acc[nt][q] = 0.f;

        // stage chunks 0 and 1 (h split hi/lo)
        for (int L = tid; L < 1024; L += 768) {
            int ch = L >> 9;
            int i = L & 511;
            int r = i >> 3, q = i & 7;
            float4 v = __ldcg((const float4*)(hs + (size_t)r * HH + ch * 32 + q * 4));
            float h0 = cvt_tf32(v.x), h1 = cvt_tf32(v.y), h2 = cvt_tf32(v.z), h3 = cvt_tf32(v.w);
            float l0 = cvt_tf32(v.x - h0), l1 = cvt_tf32(v.y - h1);
            float l2 = cvt_tf32(v.z - h2), l3 = cvt_tf32(v.w - h3);
            int kk = q * 4;
            int w = kk ^ ((r & 7) * 4);
            float2* row = (ch ? Abuf1 : Abuf0) + r * 32;
            *(float4*)&row[w]     = make_float4(h0, l0, h1, l1);
            *(float4*)&row[w + 2] = make_float4(h2, l2, h3, l3);
        }
        __syncthreads();

        const float2* Ab = kh ? Abuf1 : Abuf0;
        const int arow = rw * 16 + gid;

        for (int it = 0; it < 8; it++) {
            bool hasNext = (it + 1 < 8);
            float4 pf0, pf1;
            int r0 = 0, q0 = 0, c0 = 0, r1 = 0, q1 = 0, c1 = 0;
            bool hv1 = false;
            if (hasNext) {
                int base = (it + 1) * 2;
                int L = tid;
                c0 = base + (L >> 9); { int i = L & 511; r0 = i >> 3; q0 = i & 7; }
                pf0 = __ldcg((const float4*)(hs + (size_t)r0 * HH + c0 * 32 + q0 * 4));
                int L2 = tid + 768;
                if (L2 < 1024) {
                    c1 = base + (L2 >> 9); { int i = L2 & 511; r1 = i >> 3; q1 = i & 7; }
                    pf1 = __ldcg((const float4*)(hs + (size_t)r1 * HH + c1 * 32 + q1 * 4));
                    hv1 = true;
                }
            }

            int cc = it * 2 + kh;
            #pragma unroll
            for (int ck = 0; ck < 4; ck++) {
                int k8 = ck * 8;
                float2 a0 = Ab[arow * 32 + ((k8 + tig) ^ sxa)];
                float2 a1 = Ab[(arow + 8) * 32 + ((k8 + tig) ^ sxa)];
                float2 a2 = Ab[arow * 32 + ((k8 + 4 + tig) ^ sxa)];
                float2 a3 = Ab[(arow + 8) * 32 + ((k8 + 4 + tig) ^ sxa)];
                #pragma unroll
                for (int nt = 0; nt < 2; nt++) {
                    int wr = gw * 16 + nt * 8 + gid;
                    const float* Wb = Wsm + (size_t)wr * HH + cc * 32;
                    float b0 = Wb[(k8 + tig) ^ sxa];
                    float b1 = Wb[(k8 + 4 + tig) ^ sxa];
                    // hi @ Whi
                    mma8(acc[nt], FU(a0.x), FU(a1.x), FU(a2.x), FU(a3.x), FU(b0), FU(b1));
                    // lo @ Whi
                    mma8(acc[nt], FU(a0.y), FU(a1.y), FU(a2.y), FU(a3.y), FU(b0), FU(b1));
                }
            }
            __syncthreads();

            if (hasNext) {
                {
                    float4 v = pf0;
                    float h0 = cvt_tf32(v.x), h1 = cvt_tf32(v.y), h2 = cvt_tf32(v.z), h3 = cvt_tf32(v.w);
                    float l0 = cvt_tf32(v.x - h0), l1 = cvt_tf32(v.y - h1);
                    float l2 = cvt_tf32(v.z - h2), l3 = cvt_tf32(v.w - h3);
                    int kk = q0 * 4;
                    int w = kk ^ ((r0 & 7) * 4);
                    float2* row = ((c0 & 1) ? Abuf1 : Abuf0) + r0 * 32;
                    *(float4*)&row[w]     = make_float4(h0, l0, h1, l1);
                    *(float4*)&row[w + 2] = make_float4(h2, l2, h3, l3);
                }
                if (hv1) {
                    float4 v = pf1;
                    float h0 = cvt_tf32(v.x), h1 = cvt_tf32(v.y), h2 = cvt_tf32(v.z), h3 = cvt_tf32(v.w);
                    float l0 = cvt_tf32(v.x - h0), l1 = cvt_tf32(v.y - h1);
                    float l2 = cvt_tf32(v.z - h2), l3 = cvt_tf32(v.w - h3);
                    int kk = q1 * 4;
                    int w = kk ^ ((r1 & 7) * 4);
                    float2* row = ((c1 & 1) ? Abuf1 : Abuf0) + r1 * 32;
                    *(float4*)&row[w]     = make_float4(h0, l0, h1, l1);
                    *(float4*)&row[w + 2] = make_float4(h2, l2, h3, l3);
                }
                __syncthreads();
            }
        }

        // stage partial gate outputs: [kh][gate][64][17]
        {
            float* sgp = sg + ((size_t)kh * 3 + gw) * 64 * 17;
            #pragma unroll
            for (int nt = 0; nt < 2; nt++) {
                int col = nt * 8 + tig * 2;
                sgp[arow * 17 + col]     = acc[nt][0];
                sgp[arow * 17 + col + 1] = acc[nt][1];
                sgp[(arow + 8) * 17 + col]     = acc[nt][2];
                sgp[(arow + 8) * 17 + col + 1] = acc[nt][3];
            }
        }
        __syncthreads();

        for (int i = tid; i < 1024; i += 768) {
            int row = i >> 4, col = i & 15;
            int bidx = rt * 64 + row;
            int gcol = ct * 16 + col;
            float hr = sg[0 * 64 * 17 + row * 17 + col] + sg[(3 + 0) * 64 * 17 + row * 17 + col] + bhh[gcol];
            float hz = sg[1 * 64 * 17 + row * 17 + col] + sg[(3 + 1) * 64 * 17 + row * 17 + col] + bhh[HH + gcol];
            float hn = sg[2 * 64 * 17 + row * 17 + col] + sg[(3 + 2) * 64 * 17 + row * 17 + col] + bhh[2 * HH + gcol];
            const float* xrow = xg + ((size_t)tt * BB + bidx) * GG;
            float xr = xrow[gcol], xz = xrow[HH + gcol], xn = xrow[2 * HH + gcol];
            float hp = __ldcg(src + (size_t)(rowbase + row) * HH + gcol);
            float rr = 1.f / (1.f + expf(-(xr + hr)));
            float zz = 1.f / (1.f + expf(-(xz + hz)));
            float nn = tanhf(xn + rr * hn);
            float hnew = (1.f - zz) * nn + zz * hp;
            dst[(size_t)(rowbase + row) * HH + gcol] = hnew;
            y[((size_t)tt * BB + bidx) * DD1 + dir * HH + gcol] = hnew;
            if (t == SS - 1)
                hid_out[((size_t)dir * BB + bidx) * HH + gcol] = hnew;
        }

        if (t < SS - 1) group_barrier(grp, &ls);
    }
}

// ---------------- host orchestration ----------------
extern "C" void kernel_launch(void* const* d_in, const int* in_sizes, int n_in,
                              void* d_out, int out_size) {
    const int*   i1    = (const int*)d_in[0];
    const int*   i2    = (const int*)d_in[1];
    const int*   pg    = (const int*)d_in[3];
    const float* emb1  = (const float*)d_in[4];
    const float* emb2  = (const float*)d_in[5];
    const float* wih0f = (const float*)d_in[6];
    const float* whh0f = (const float*)d_in[7];
    const float* bih0f = (const float*)d_in[8];
    const float* bhh0f = (const float*)d_in[9];
    const float* wih0b = (const float*)d_in[10];
    const float* whh0b = (const float*)d_in[11];
    const float* bih0b = (const float*)d_in[12];
    const float* bhh0b = (const float*)d_in[13];
    const float* wih1f = (const float*)d_in[14];
    const float* whh1f = (const float*)d_in[15];
    const float* bih1f = (const float*)d_in[16];
    const float* bhh1f = (const float*)d_in[17];
    const float* wih1b = (const float*)d_in[18];
    const float* whh1b = (const float*)d_in[19];
    const float* bih1b = (const float*)d_in[20];
    const float* bhh1b = (const float*)d_in[21];
    const float* fc1w  = (const float*)d_in[22];
    const float* fc1b  = (const float*)d_in[23];
    const float* fc2w  = (const float*)d_in[24];
    const float* fc2b  = (const float*)d_in[25];
    const float* outw  = (const float*)d_in[26];
    const float* outb  = (const float*)d_in[27];
    float* out = (float*)d_out;

    float *x0, *xgf, *xgb, *y0, *y1, *h0, *h1, *an, *dinv, *node, *node2, *ni, *tmp, *nodeT;
    cudaGetSymbolAddress((void**)&x0,   g_x0);
    cudaGetSymbolAddress((void**)&xgf,  g_xgf);
    cudaGetSymbolAddress((void**)&xgb,  g_xgb);
    cudaGetSymbolAddress((void**)&y0,   g_y0);
    cudaGetSymbolAddress((void**)&y1,   g_y1);
    cudaGetSymbolAddress((void**)&h0,   g_h0);
    cudaGetSymbolAddress((void**)&h1,   g_h1);
    cudaGetSymbolAddress((void**)&an,   g_an);
    cudaGetSymbolAddress((void**)&dinv, g_dinv);
    cudaGetSymbolAddress((void**)&node, g_node);
    cudaGetSymbolAddress((void**)&node2,g_node2);
    cudaGetSymbolAddress((void**)&ni,   g_ni);
    cudaGetSymbolAddress((void**)&tmp,  g_tmp);
    cudaGetSymbolAddress((void**)&nodeT,g_nodeT);

    cudaFuncSetAttribute(gru_persistent,
                         cudaFuncAttributeMaxDynamicSharedMemorySize, GRU_SMEM);
    cudaFuncSetAttribute(mma_gemm_nt<false,false>,
                         cudaFuncAttributeMaxDynamicSharedMemorySize, GEMM_SMEM);
    cudaFuncSetAttribute(mma_gemm_nt<true,false>,
                         cudaFuncAttributeMaxDynamicSharedMemorySize, GEMM_SMEM);
    cudaFuncSetAttribute(mma_gemm_nt<true,true>,
                         cudaFuncAttributeMaxDynamicSharedMemorySize, GEMM_SMEM);

    float* hid_base = out + (size_t)SB * HH;

    // 1) embedding
    embed_kernel<<<(SB * EE + 255) / 256, 256>>>(i1, i2, emb1, emb2, x0);

    // 2) layer0 input gates (fused f+b, N=3072)
    dim3 gG2(2 * GG / 128, SB / 128, 1);
    mma_gemm_nt<false,false><<<gG2, 256, GEMM_SMEM>>>(
        x0, nullptr, wih0f, wih0b, bih0f, bih0b,
        xgf, xgb, EE, 0, GG, EE, EE, GG, 0, 0, 0);

    // 3) layer0 recurrence (persistent)
    cudaMemsetAsync(h0, 0, (size_t)2 * BB * HH * sizeof(float));
    gru_persistent<<<128, 768, GRU_SMEM>>>(xgf, xgb, whh0f, whh0b, bhh0f, bhh0b,
                                           h0, h1, y0, hid_base);

    // 4) layer1 input gates (fused f+b)
    mma_gemm_nt<false,false><<<gG2, 256, GEMM_SMEM>>>(
        y0, nullptr, wih1f, wih1b, bih1f, bih1b,
        xgf, xgb, DD1, 0, GG, DD1, DD1, GG, 0, 0, 0);

    // 5) layer1 recurrence
    cudaMemsetAsync(h0, 0, (size_t)2 * BB * HH * sizeof(float));
    gru_persistent<<<128, 768, GRU_SMEM>>>(xgf, xgb, whh1f, whh1b, bhh1f, bhh1b,
                                           h0, h1, y1, hid_base + 2 * BB * HH);

    // 6) direction sum -> node [B,S,H]
    sumdir_kernel<<<(BB * SS * HH + 255) / 256, 256>>>(y1, node);

    // 7) normalized adjacency
    dinv_kernel<<<BB * SS / 8, 256>>>(pg, dinv);
    an_kernel<<<(BB * SS * SS + 255) / 256, 256>>>(pg, dinv, an);

    // 8) GNN hops
    dim3 gH(HH / 128, SB / 128, 1);
    dim3 gAn(HH / 128, SS / 128, BB);
    dim3 gT(HH / 32, SS / 32, BB);
    float* cur = node; float* nxt = node2;
    for (int i = 0; i < 2; i++) {
        const float* f1w = fc1w + (size_t)i * HH * HH;
        const float* f1b = fc1b + (size_t)i * HH;
        const float* f2w = fc2w + (size_t)i * HH * HH;
        const float* f2b = fc2b + (size_t)i * HH;
        const float* ow  = outw + (size_t)i * HH * DD1;
        const float* ob  = outb + (size_t)i * HH;

        transpose_bsh<<<gT, dim3(32, 8)>>>(cur, nodeT);
        mma_gemm_nt<false,false><<<gAn, 256, GEMM_SMEM>>>(
            an, nullptr, nodeT, nullptr, nullptr, nullptr, tmp, nullptr,
            SS, 0, 0, SS, SS, HH,
            (long long)SS * SS, (long long)HH * SS, (long long)SS * HH);
        mma_gemm_nt<true,false><<<gH, 256, GEMM_SMEM>>>(
            tmp, nullptr, f1w, nullptr, f1b, nullptr, ni, nullptr,
            HH, 0, 0, HH, HH, HH, 0, 0, 0);

        transpose_bsh<<<gT, dim3(32, 8)>>>(ni, nodeT);
        mma_gemm_nt<false,false><<<gAn, 256, GEMM_SMEM>>>(
            an, nullptr, nodeT, nullptr, nullptr, nullptr, tmp, nullptr,
            SS, 0, 0, SS, SS, HH,
            (long long)SS * SS, (long long)HH * SS, (long long)SS * HH);
        mma_gemm_nt<true,false><<<gH, 256, GEMM_SMEM>>>(
            tmp, nullptr, f2w, nullptr, f2b, nullptr, ni, nullptr,
            HH, 0, 0, HH, HH, HH, 0, 0, 0);

        // fused: out = relu([cur|ni] @ ow^T + ob), K=1024, split at 512
        if (i == 0) {
            mma_gemm_nt<true,false><<<gH, 256, GEMM_SMEM>>>(
                cur, ni, ow, nullptr, ob, nullptr, nxt, nullptr,
                DD1, HH, 0, HH, DD1, HH, 0, 0, 0);
            float* tptr = cur; cur = nxt; nxt = tptr;
        } else {
            // final hop: write pade_outputs [S,B,H] directly (fused transpose)
            mma_gemm_nt<true,true><<<gH, 256, GEMM_SMEM>>>(
                cur, ni, ow, nullptr, ob, nullptr, out, nullptr,
                DD1, HH, 0, HH, DD1, HH, 0, 0, 0);
        }
    }
}

// round 14
// speedup vs baseline: 1.3765x; 1.1933x over previous
#include <cuda_runtime.h>
#include <math.h>
#include <stdint.h>

#define SS 256
#define BB 128
#define HH 512
#define GG 1536
#define EE 192
#define DD1 1024
#define SB (SS*BB)   // 32768
#define PAD 20       // smem row stride in floats (conflict-free: 20r mod 32 distinct)
#define NSTAGE 3
#define GEMM_SMEM (2 * NSTAGE * 128 * PAD * 4)   // 61440 B

// ---------------- scratch (__device__ globals, no allocation) ----------------
__device__ float g_x0 [SB*EE];
__device__ float g_xgf[SB*GG];
__device__ float g_xgb[SB*GG];
__device__ float g_y0 [SB*DD1];
__device__ float g_y1 [SB*DD1];
__device__ float g_h0 [2*BB*HH];
__device__ float g_h1 [2*BB*HH];
__device__ float g_an [BB*SS*SS];
__device__ float g_dinv[BB*SS];
__device__ float g_node [BB*SS*HH];
__device__ float g_node2[BB*SS*HH];
__device__ float g_ni   [BB*SS*HH];
__device__ float g_tmp  [BB*SS*HH];
__device__ float g_nodeT[BB*HH*SS];

// group-barrier state (4 groups of 32 CTAs; self-consistent across replays)
__device__ unsigned g_bc[128];
__device__ volatile unsigned g_bs[128];

__device__ __forceinline__ float cvt_tf32(float x) {
    uint32_t r;
    asm("cvt.rna.tf32.f32 %0, %1;" : "=r"(r) : "f"(x));
    return __uint_as_float(r);
}

__device__ __forceinline__ uint32_t smem_u32(const void* p) {
    uint32_t a;
    asm("{ .reg .u64 t; cvta.to.shared.u64 t, %1; cvt.u32.u64 %0, t; }" : "=r"(a) : "l"(p));
    return a;
}

__device__ __forceinline__ void cpasync16(uint32_t dst, const void* src) {
    asm volatile("cp.async.cg.shared.global [%0], [%1], 16;" :: "r"(dst), "l"(src));
}
#define CP_COMMIT() asm volatile("cp.async.commit_group;" ::: "memory")
#define CP_WAIT1()  asm volatile("cp.async.wait_group 1;" ::: "memory")

// ---------------- small elementwise kernels ----------------
__global__ void embed_kernel(const int* __restrict__ i1, const int* __restrict__ i2,
                             const float* __restrict__ emb1, const float* __restrict__ emb2,
                             float* __restrict__ x0) {
    int idx = blockIdx.x * blockDim.x + threadIdx.x;
    if (idx >= SB * EE) return;
    int t = idx / EE, e = idx - t * EE;
    if (e < 128) {
        x0[idx] = emb1[(size_t)i1[t] * 128 + e];
    } else {
        int v = i2[t];
        x0[idx] = (v == 0) ? 0.f : emb2[(size_t)v * 64 + (e - 128)];
    }
}

__global__ void dinv_kernel(const int* __restrict__ pg, float* __restrict__ dinv) {
    int row  = blockIdx.x * 8 + (threadIdx.x >> 5);
    int lane = threadIdx.x & 31;
    int b = row >> 8, s = row & 255;
    const int* ar = pg + ((size_t)b * 3 + 2) * (SS * SS) + (size_t)s * SS;
    int acc = 0;
    for (int t = lane; t < SS; t += 32) acc += ar[t];
    #pragma unroll
    for (int o = 16; o; o >>= 1) acc += __shfl_down_sync(0xffffffffu, acc, o);
    if (lane == 0) dinv[row] = rsqrtf((float)acc + 1.0f);
}

__global__ void an_kernel(const int* __restrict__ pg, const float* __restrict__ dinv,
                          float* __restrict__ an) {
    int idx = blockIdx.x * blockDim.x + threadIdx.x;
    if (idx >= BB * SS * SS) return;
    int t = idx & 255, s = (idx >> 8) & 255, b = idx >> 16;
    float a = (float)pg[((size_t)b * 3 + 2) * (SS * SS) + s * SS + t] + (s == t ? 1.f : 0.f);
    an[idx] = a * dinv[b * SS + s] * dinv[b * SS + t];
}

__global__ void sumdir_kernel(const float* __restrict__ y, float* __restrict__ node) {
    int idx = blockIdx.x * blockDim.x + threadIdx.x;
    if (idx >= BB * SS * HH) return;
    int j = idx & 511, s = (idx >> 9) & 255, b = idx >> 17;
    size_t yi = ((size_t)s * BB + b) * DD1 + j;
    node[idx] = y[yi] + y[yi + HH];
}

// [B,S,H] -> [B,H,S]
__global__ void transpose_bsh(const float* __restrict__ src, float* __restrict__ dst) {
    __shared__ float t[32][33];
    int b = blockIdx.z;
    int s0 = blockIdx.y * 32, h0 = blockIdx.x * 32;
    src += (size_t)b * SS * HH;
    dst += (size_t)b * SS * HH;
    int x = threadIdx.x, y = threadIdx.y;
    #pragma unroll
    for (int i = 0; i < 32; i += 8) t[y + i][x] = src[(size_t)(s0 + y + i) * HH + h0 + x];
    __syncthreads();
    #pragma unroll
    for (int i = 0; i < 32; i += 8) dst[(size_t)(h0 + y + i) * SS + s0 + x] = t[x][y + i];
}

// ================= tf32 mma helpers =================
__device__ __forceinline__ void mma8(float* d, uint32_t a0, uint32_t a1, uint32_t a2,
                                     uint32_t a3, uint32_t b0, uint32_t b1) {
    asm volatile(
        "mma.sync.aligned.m16n8k8.row.col.f32.tf32.tf32.f32 "
        "{%0,%1,%2,%3}, {%4,%5,%6,%7}, {%8,%9}, {%0,%1,%2,%3};"
        : "+f"(d[0]), "+f"(d[1]), "+f"(d[2]), "+f"(d[3])
        : "r"(a0), "r"(a1), "r"(a2), "r"(a3), "r"(b0), "r"(b1));
}
#define FU(x) __float_as_uint(x)
#define CV(x) __float_as_uint(cvt_tf32(x))

// ============ tf32 mma.sync NT GEMM — R12-proven (cp.async pipe, fused transpose) ========
template<bool RELU, bool TRANSOUT>
__global__ void __launch_bounds__(256) mma_gemm_nt(
    const float* __restrict__ A, const float* __restrict__ A2,
    const float* __restrict__ W, const float* __restrict__ W2,
    const float* __restrict__ bias, const float* __restrict__ bias2,
    float* __restrict__ C, float* __restrict__ C2,
    int K, int K1, int Nsplit, int lda, int ldw, int ldc,
    long long sA, long long sW, long long sC)
{
    extern __shared__ float smg[];
    const int SLOT = 128 * PAD;

    int tid = threadIdx.x;
    int lane = tid & 31, warp = tid >> 5;
    int wm = warp >> 2, wn = warp & 3;
    int groupID = lane >> 2, tig = lane & 3;
    int n0 = blockIdx.x * 128, m0 = blockIdx.y * 128;
    if (W2 && n0 >= Nsplit) {
        W = W2; bias = bias2; C = C2; n0 -= Nsplit;
    }
    int z = blockIdx.z;
    A += (size_t)z * (size_t)sA;
    W += (size_t)z * (size_t)sW;
    C += (size_t)z * (size_t)sC;

    int lr = tid >> 2;
    int lc = (tid & 3) * 4;

    const int arb = wm * 64;
    const int wcb = wn * 32;

    uint32_t smb = smem_u32(smg);
    uint32_t dA0 = smb + (uint32_t)(lr * PAD + lc) * 4u;
    uint32_t dA1 = smb + (uint32_t)((lr + 64) * PAD + lc) * 4u;
    uint32_t dW0 = dA0 + (uint32_t)(NSTAGE * SLOT) * 4u;
    uint32_t dW1 = dA1 + (uint32_t)(NSTAGE * SLOT) * 4u;

    float acc[4][4][4];
    #pragma unroll
    for (int mt = 0; mt < 4; mt++)
        #pragma unroll
        for (int nt = 0; nt < 4; nt++)
            #pragma unroll
            for (int q = 0; q < 4; q++) acc[mt][nt][q] = 0.f;

    auto aload = [&](int c, int s) {
        int koff = c * 16 + lc;
        const float* Ab;
        if (A2 && koff >= K1)
            Ab = A2 + (size_t)(m0 + lr) * lda + (koff - K1);
        else
            Ab = A + (size_t)(m0 + lr) * lda + koff;
        const float* Wb = W + (size_t)(n0 + lr) * ldw + c * 16 + lc;
        uint32_t so = (uint32_t)(s * SLOT) * 4u;
        cpasync16(dA0 + so, Ab);
        cpasync16(dA1 + so, Ab + (size_t)64 * lda);
        cpasync16(dW0 + so, Wb);
        cpasync16(dW1 + so, Wb + (size_t)64 * ldw);
        CP_COMMIT();
    };

    int Cn = K >> 4;
    aload(0, 0);
    aload(1, 1);

    for (int c = 0; c < Cn; c++) {
        CP_WAIT1();
        __syncthreads();

        int slot = c % NSTAGE;
        if (c + 2 < Cn) aload(c + 2, (c + 2) % NSTAGE);

        const float* As = smg + slot * SLOT;
        const float* Ws = smg + (NSTAGE + slot) * SLOT;
        #pragma unroll
        for (int ks = 0; ks < 2; ks++) {
            int k0 = ks * 8;
            float af[4][4], bf[4][2];
            #pragma unroll
            for (int mt = 0; mt < 4; mt++) {
                int rb = arb + mt * 16 + groupID;
                af[mt][0] = As[rb * PAD + k0 + tig];
                af[mt][1] = As[(rb + 8) * PAD + k0 + tig];
                af[mt][2] = As[rb * PAD + k0 + 4 + tig];
                af[mt][3] = As[(rb + 8) * PAD + k0 + 4 + tig];
            }
            #pragma unroll
            for (int nt = 0; nt < 4; nt++) {
                int cb = wcb + nt * 8 + groupID;
                bf[nt][0] = Ws[cb * PAD + k0 + tig];
                bf[nt][1] = Ws[cb * PAD + k0 + 4 + tig];
            }
            uint32_t au[4][4], bu[4][2];
            #pragma unroll
            for (int mt = 0; mt < 4; mt++) {
                au[mt][0] = CV(af[mt][0]); au[mt][1] = CV(af[mt][1]);
                au[mt][2] = CV(af[mt][2]); au[mt][3] = CV(af[mt][3]);
            }
            #pragma unroll
            for (int nt = 0; nt < 4; nt++) {
                bu[nt][0] = CV(bf[nt][0]); bu[nt][1] = CV(bf[nt][1]);
            }
            #pragma unroll
            for (int mt = 0; mt < 4; mt++)
                #pragma unroll
                for (int nt = 0; nt < 4; nt++)
                    mma8(acc[mt][nt], au[mt][0], au[mt][1], au[mt][2], au[mt][3],
                         bu[nt][0], bu[nt][1]);
        }
    }

    #pragma unroll
    for (int mt = 0; mt < 4; mt++) {
        #pragma unroll
        for (int nt = 0; nt < 4; nt++) {
            int gr = m0 + arb + mt * 16 + groupID;
            int gc = n0 + wcb + nt * 8 + tig * 2;
            float b0 = 0.f, b1 = 0.f;
            if (bias) { b0 = bias[gc]; b1 = bias[gc + 1]; }
            float v00 = acc[mt][nt][0] + b0, v01 = acc[mt][nt][1] + b1;
            float v10 = acc[mt][nt][2] + b0, v11 = acc[mt][nt][3] + b1;
            if (RELU) {
                v00 = fmaxf(v00, 0.f); v01 = fmaxf(v01, 0.f);
                v10 = fmaxf(v10, 0.f); v11 = fmaxf(v11, 0.f);
            }
            size_t i0, i1;
            if (TRANSOUT) {
                int b_  = gr >> 8, s_ = gr & 255;
                int b2_ = (gr + 8) >> 8, s2_ = (gr + 8) & 255;
                i0 = ((size_t)s_  * BB + b_ ) * ldc + gc;
                i1 = ((size_t)s2_ * BB + b2_) * ldc + gc;
            } else {
                i0 = (size_t)gr * ldc + gc;
                i1 = (size_t)(gr + 8) * ldc + gc;
            }
            *(float2*)&C[i0] = make_float2(v00, v01);
            *(float2*)&C[i1] = make_float2(v10, v11);
        }
    }
}

// ================= persistent GRU: single-term tf32 (hg = hi@Whi) =================
// Wsm: [48][512] float hi (98304 B); A bufs: 2x float[64][32] hi (8192 B each);
// sg epilogue overlay [2][3][64][17] floats (26112 B). SMEM total 124416 B.
#define GRU_SMEM 124416

__device__ __forceinline__ void group_barrier(int g, unsigned* ls) {
    __syncthreads();
    if (threadIdx.x == 0) {
        unsigned s = (*ls) ^ 1u;
        __threadfence();
        unsigned old = atomicAdd(&g_bc[g * 32], 1u);
        if (old == 31u) {
            *(volatile unsigned*)&g_bc[g * 32] = 0u;
            __threadfence();
            g_bs[g * 32] = s;
        } else {
            while (g_bs[g * 32] != s) { }
        }
        __threadfence();
        *ls = s;
    }
    __syncthreads();
}

__global__ void __launch_bounds__(768, 1) gru_persistent(
    const float* __restrict__ xgf, const float* __restrict__ xgb,
    const float* __restrict__ whhf, const float* __restrict__ whhb,
    const float* __restrict__ bhhf, const float* __restrict__ bhhb,
    float* hA, float* hB,
    float* __restrict__ y, float* __restrict__ hid_out)
{
    extern __shared__ float sm[];
    float* Wsm   = sm;                               // [48][512] hi, swizzled
    float* Abuf0 = sm + 24576;                       // [64][32] hi
    float* Abuf1 = sm + 24576 + 2048;                // [64][32] hi
    float* sg    = sm + 24576;                       // epilogue overlay [2][3][64][17]

    int tid = threadIdx.x;
    int lane = tid & 31, warp = tid >> 5;
    int gid = lane >> 2, tig = lane & 3;
    int kh = warp / 12;
    int inner = warp - kh * 12;
    int rw = inner & 3, gw = inner >> 2;

    int bid = blockIdx.x;
    int ct = bid & 31, rt = (bid >> 5) & 1, dir = bid >> 6;
    int grp = bid >> 5;
    const float* Wsrc = dir ? whhb : whhf;
    const float* bhh  = dir ? bhhb : bhhf;
    const float* xg   = dir ? xgb  : xgf;
    const int rowbase = dir * BB + rt * 64;
    const int sxa = gid * 4;

    unsigned ls = g_bs[grp * 32];

    // preload weights (tf32 hi only), swizzled
    for (int i = tid; i < 48 * 128; i += 768) {
        int lr = i >> 7;
        int q  = i & 127;
        int g = lr >> 4, j = lr & 15;
        float4 v = *(const float4*)(Wsrc + ((size_t)(g * HH + ct * 16 + j)) * HH + q * 4);
        int kk = q * 4;
        int w = (kk & ~31) + ((kk & 31) ^ ((lr & 7) * 4));
        *(float4*)&Wsm[lr * HH + w] =
            make_float4(cvt_tf32(v.x), cvt_tf32(v.y), cvt_tf32(v.z), cvt_tf32(v.w));
    }
    __syncthreads();

    for (int t = 0; t < SS; t++) {
        const float* src = (t & 1) ? hB : hA;
        float*       dst = (t & 1) ? hA : hB;
        int tt = dir ? (SS - 1 - t) : t;
        const float* hs = src + (size_t)rowbase * HH;

        float acc[2][4];
        #pragma unroll
        for (int nt = 0; nt < 2; nt++)
            #pragma unroll
            for (int q = 0; q < 4; q++) acc[nt][q] = 0.f;

        // stage chunks 0 and 1 (hi only)
        for (int L = tid; L < 1024; L += 768) {
            int ch = L >> 9;
            int i = L & 511;
            int r = i >> 3, q = i & 7;
            float4 v = __ldcg((const float4*)(hs + (size_t)r * HH + ch * 32 + q * 4));
            int kk = q * 4;
            int w = kk ^ ((r & 7) * 4);
            float* row = (ch ? Abuf1 : Abuf0) + r * 32;
            *(float4*)&row[w] =
                make_float4(cvt_tf32(v.x), cvt_tf32(v.y), cvt_tf32(v.z), cvt_tf32(v.w));
        }
        __syncthreads();

        const float* Ab = kh ? Abuf1 : Abuf0;
        const int arow = rw * 16 + gid;

        for (int it = 0; it < 8; it++) {
            bool hasNext = (it + 1 < 8);
            float4 pf0, pf1;
            int r0 = 0, q0 = 0, c0 = 0, r1 = 0, q1 = 0, c1 = 0;
            bool hv1 = false;
            if (hasNext) {
                int base = (it + 1) * 2;
                int L = tid;
                c0 = base + (L >> 9); { int i = L & 511; r0 = i >> 3; q0 = i & 7; }
                pf0 = __ldcg((const float4*)(hs + (size_t)r0 * HH + c0 * 32 + q0 * 4));
                int L2 = tid + 768;
                if (L2 < 1024) {
                    c1 = base + (L2 >> 9); { int i = L2 & 511; r1 = i >> 3; q1 = i & 7; }
                    pf1 = __ldcg((const float4*)(hs + (size_t)r1 * HH + c1 * 32 + q1 * 4));
                    hv1 = true;
                }
            }

            int cc = it * 2 + kh;
            #pragma unroll
            for (int ck = 0; ck < 4; ck++) {
                int k8 = ck * 8;
                float a0 = Ab[arow * 32 + ((k8 + tig) ^ sxa)];
                float a1 = Ab[(arow + 8) * 32 + ((k8 + tig) ^ sxa)];
                float a2 = Ab[arow * 32 + ((k8 + 4 + tig) ^ sxa)];
                float a3 = Ab[(arow + 8) * 32 + ((k8 + 4 + tig) ^ sxa)];
                #pragma unroll
                for (int nt = 0; nt < 2; nt++) {
                    int wr = gw * 16 + nt * 8 + gid;
                    const float* Wb = Wsm + (size_t)wr * HH + cc * 32;
                    float b0 = Wb[(k8 + tig) ^ sxa];
                    float b1 = Wb[(k8 + 4 + tig) ^ sxa];
                    mma8(acc[nt], FU(a0), FU(a1), FU(a2), FU(a3), FU(b0), FU(b1));
                }
            }
            __syncthreads();

            if (hasNext) {
                {
                    float4 v = pf0;
                    int kk = q0 * 4;
                    int w = kk ^ ((r0 & 7) * 4);
                    float* row = ((c0 & 1) ? Abuf1 : Abuf0) + r0 * 32;
                    *(float4*)&row[w] =
                        make_float4(cvt_tf32(v.x), cvt_tf32(v.y), cvt_tf32(v.z), cvt_tf32(v.w));
                }
                if (hv1) {
                    float4 v = pf1;
                    int kk = q1 * 4;
                    int w = kk ^ ((r1 & 7) * 4);
                    float* row = ((c1 & 1) ? Abuf1 : Abuf0) + r1 * 32;
                    *(float4*)&row[w] =
                        make_float4(cvt_tf32(v.x), cvt_tf32(v.y), cvt_tf32(v.z), cvt_tf32(v.w));
                }
                __syncthreads();
            }
        }

        // stage partial gate outputs: [kh][gate][64][17]
        {
            float* sgp = sg + ((size_t)kh * 3 + gw) * 64 * 17;
            #pragma unroll
            for (int nt = 0; nt < 2; nt++) {
                int col = nt * 8 + tig * 2;
                sgp[arow * 17 + col]     = acc[nt][0];
                sgp[arow * 17 + col + 1] = acc[nt][1];
                sgp[(arow + 8) * 17 + col]     = acc[nt][2];
                sgp[(arow + 8) * 17 + col + 1] = acc[nt][3];
            }
        }
        __syncthreads();

        for (int i = tid; i < 1024; i += 768) {
            int row = i >> 4, col = i & 15;
            int bidx = rt * 64 + row;
            int gcol = ct * 16 + col;
            float hr = sg[0 * 64 * 17 + row * 17 + col] + sg[(3 + 0) * 64 * 17 + row * 17 + col] + bhh[gcol];
            float hz = sg[1 * 64 * 17 + row * 17 + col] + sg[(3 + 1) * 64 * 17 + row * 17 + col] + bhh[HH + gcol];
            float hn = sg[2 * 64 * 17 + row * 17 + col] + sg[(3 + 2) * 64 * 17 + row * 17 + col] + bhh[2 * HH + gcol];
            const float* xrow = xg + ((size_t)tt * BB + bidx) * GG;
            float xr = xrow[gcol], xz = xrow[HH + gcol], xn = xrow[2 * HH + gcol];
            float hp = __ldcg(src + (size_t)(rowbase + row) * HH + gcol);
            float rr = 1.f / (1.f + expf(-(xr + hr)));
            float zz = 1.f / (1.f + expf(-(xz + hz)));
            float nn = tanhf(xn + rr * hn);
            float hnew = (1.f - zz) * nn + zz * hp;
            dst[(size_t)(rowbase + row) * HH + gcol] = hnew;
            y[((size_t)tt * BB + bidx) * DD1 + dir * HH + gcol] = hnew;
            if (t == SS - 1)
                hid_out[((size_t)dir * BB + bidx) * HH + gcol] = hnew;
        }

        if (t < SS - 1) group_barrier(grp, &ls);
    }
}

// ---------------- host orchestration ----------------
extern "C" void kernel_launch(void* const* d_in, const int* in_sizes, int n_in,
                              void* d_out, int out_size) {
    const int*   i1    = (const int*)d_in[0];
    const int*   i2    = (const int*)d_in[1];
    const int*   pg    = (const int*)d_in[3];
    const float* emb1  = (const float*)d_in[4];
    const float* emb2  = (const float*)d_in[5];
    const float* wih0f = (const float*)d_in[6];
    const float* whh0f = (const float*)d_in[7];
    const float* bih0f = (const float*)d_in[8];
    const float* bhh0f = (const float*)d_in[9];
    const float* wih0b = (const float*)d_in[10];
    const float* whh0b = (const float*)d_in[11];
    const float* bih0b = (const float*)d_in[12];
    const float* bhh0b = (const float*)d_in[13];
    const float* wih1f = (const float*)d_in[14];
    const float* whh1f = (const float*)d_in[15];
    const float* bih1f = (const float*)d_in[16];
    const float* bhh1f = (const float*)d_in[17];
    const float* wih1b = (const float*)d_in[18];
    const float* whh1b = (const float*)d_in[19];
    const float* bih1b = (const float*)d_in[20];
    const float* bhh1b = (const float*)d_in[21];
    const float* fc1w  = (const float*)d_in[22];
    const float* fc1b  = (const float*)d_in[23];
    const float* fc2w  = (const float*)d_in[24];
    const float* fc2b  = (const float*)d_in[25];
    const float* outw  = (const float*)d_in[26];
    const float* outb  = (const float*)d_in[27];
    float* out = (float*)d_out;

    float *x0, *xgf, *xgb, *y0, *y1, *h0, *h1, *an, *dinv, *node, *node2, *ni, *tmp, *nodeT;
    cudaGetSymbolAddress((void**)&x0,   g_x0);
    cudaGetSymbolAddress((void**)&xgf,  g_xgf);
    cudaGetSymbolAddress((void**)&xgb,  g_xgb);
    cudaGetSymbolAddress((void**)&y0,   g_y0);
    cudaGetSymbolAddress((void**)&y1,   g_y1);
    cudaGetSymbolAddress((void**)&h0,   g_h0);
    cudaGetSymbolAddress((void**)&h1,   g_h1);
    cudaGetSymbolAddress((void**)&an,   g_an);
    cudaGetSymbolAddress((void**)&dinv, g_dinv);
    cudaGetSymbolAddress((void**)&node, g_node);
    cudaGetSymbolAddress((void**)&node2,g_node2);
    cudaGetSymbolAddress((void**)&ni,   g_ni);
    cudaGetSymbolAddress((void**)&tmp,  g_tmp);
    cudaGetSymbolAddress((void**)&nodeT,g_nodeT);

    cudaFuncSetAttribute(gru_persistent,
                         cudaFuncAttributeMaxDynamicSharedMemorySize, GRU_SMEM);
    cudaFuncSetAttribute(mma_gemm_nt<false,false>,
                         cudaFuncAttributeMaxDynamicSharedMemorySize, GEMM_SMEM);
    cudaFuncSetAttribute(mma_gemm_nt<true,false>,
                         cudaFuncAttributeMaxDynamicSharedMemorySize, GEMM_SMEM);
    cudaFuncSetAttribute(mma_gemm_nt<true,true>,
                         cudaFuncAttributeMaxDynamicSharedMemorySize, GEMM_SMEM);

    float* hid_base = out + (size_t)SB * HH;

    // 1) embedding
    embed_kernel<<<(SB * EE + 255) / 256, 256>>>(i1, i2, emb1, emb2, x0);

    // 2) layer0 input gates (fused f+b, N=3072)
    dim3 gG2(2 * GG / 128, SB / 128, 1);
    mma_gemm_nt<false,false><<<gG2, 256, GEMM_SMEM>>>(
        x0, nullptr, wih0f, wih0b, bih0f, bih0b,
        xgf, xgb, EE, 0, GG, EE, EE, GG, 0, 0, 0);

    // 3) layer0 recurrence (persistent)
    cudaMemsetAsync(h0, 0, (size_t)2 * BB * HH * sizeof(float));
    gru_persistent<<<128, 768, GRU_SMEM>>>(xgf, xgb, whh0f, whh0b, bhh0f, bhh0b,
                                           h0, h1, y0, hid_base);

    // 4) layer1 input gates (fused f+b)
    mma_gemm_nt<false,false><<<gG2, 256, GEMM_SMEM>>>(
        y0, nullptr, wih1f, wih1b, bih1f, bih1b,
        xgf, xgb, DD1, 0, GG, DD1, DD1, GG, 0, 0, 0);

    // 5) layer1 recurrence
    cudaMemsetAsync(h0, 0, (size_t)2 * BB * HH * sizeof(float));
    gru_persistent<<<128, 768, GRU_SMEM>>>(xgf, xgb, whh1f, whh1b, bhh1f, bhh1b,
                                           h0, h1, y1, hid_base + 2 * BB * HH);

    // 6) direction sum -> node [B,S,H]
    sumdir_kernel<<<(BB * SS * HH + 255) / 256, 256>>>(y1, node);

    // 7) normalized adjacency
    dinv_kernel<<<BB * SS / 8, 256>>>(pg, dinv);
    an_kernel<<<(BB * SS * SS + 255) / 256, 256>>>(pg, dinv, an);

    // 8) GNN hops
    dim3 gH(HH / 128, SB / 128, 1);
    dim3 gAn(HH / 128, SS / 128, BB);
    dim3 gT(HH / 32, SS / 32, BB);
    float* cur = node; float* nxt = node2;
    for (int i = 0; i < 2; i++) {
        const float* f1w = fc1w + (size_t)i * HH * HH;
        const float* f1b = fc1b + (size_t)i * HH;
        const float* f2w = fc2w + (size_t)i * HH * HH;
        const float* f2b = fc2b + (size_t)i * HH;
        const float* ow  = outw + (size_t)i * HH * DD1;
        const float* ob  = outb + (size_t)i * HH;

        transpose_bsh<<<gT, dim3(32, 8)>>>(cur, nodeT);
        mma_gemm_nt<false,false><<<gAn, 256, GEMM_SMEM>>>(
            an, nullptr, nodeT, nullptr, nullptr, nullptr, tmp, nullptr,
            SS, 0, 0, SS, SS, HH,
            (long long)SS * SS, (long long)HH * SS, (long long)SS * HH);
        mma_gemm_nt<true,false><<<gH, 256, GEMM_SMEM>>>(
            tmp, nullptr, f1w, nullptr, f1b, nullptr, ni, nullptr,
            HH, 0, 0, HH, HH, HH, 0, 0, 0);

        transpose_bsh<<<gT, dim3(32, 8)>>>(ni, nodeT);
        mma_gemm_nt<false,false><<<gAn, 256, GEMM_SMEM>>>(
            an, nullptr, nodeT, nullptr, nullptr, nullptr, tmp, nullptr,
            SS, 0, 0, SS, SS, HH,
            (long long)SS * SS, (long long)HH * SS, (long long)SS * HH);
        mma_gemm_nt<true,false><<<gH, 256, GEMM_SMEM>>>(
            tmp, nullptr, f2w, nullptr, f2b, nullptr, ni, nullptr,
            HH, 0, 0, HH, HH, HH, 0, 0, 0);

        // fused: out = relu([cur|ni] @ ow^T + ob), K=1024, split at 512
        if (i == 0) {
            mma_gemm_nt<true,false><<<gH, 256, GEMM_SMEM>>>(
                cur, ni, ow, nullptr, ob, nullptr, nxt, nullptr,
                DD1, HH, 0, HH, DD1, HH, 0, 0, 0);
            float* tptr = cur; cur = nxt; nxt = tptr;
        } else {
            // final hop: write pade_outputs [S,B,H] directly (fused transpose)
            mma_gemm_nt<true,true><<<gH, 256, GEMM_SMEM>>>(
                cur, ni, ow, nullptr, ob, nullptr, out, nullptr,
                DD1, HH, 0, HH, DD1, HH, 0, 0, 0);
        }
    }
}

// round 15
// speedup vs baseline: 1.4085x; 1.0232x over previous
#include <cuda_runtime.h>
#include <math.h>
#include <stdint.h>

#define SS 256
#define BB 128
#define HH 512
#define GG 1536
#define EE 192
#define DD1 1024
#define SB (SS*BB)   // 32768
#define PAD 20       // smem row stride in floats (conflict-free: 20r mod 32 distinct)
#define NSTAGE 3
#define GEMM_SMEM (2 * NSTAGE * 128 * PAD * 4)   // 61440 B

// ---------------- scratch (__device__ globals, no allocation) ----------------
__device__ float g_x0 [SB*EE];
__device__ float g_xgf[SB*GG];
__device__ float g_xgb[SB*GG];
__device__ float g_y0 [SB*DD1];
__device__ float g_y1 [SB*DD1];
__device__ float g_h0 [2*BB*HH];
__device__ float g_h1 [2*BB*HH];
__device__ float g_an [BB*SS*SS];
__device__ float g_dinv[BB*SS];
__device__ float g_node [BB*SS*HH];
__device__ float g_node2[BB*SS*HH];
__device__ float g_ni   [BB*SS*HH];
__device__ float g_tmp  [BB*SS*HH];
__device__ float g_nodeT[BB*HH*SS];
// pre-rounded (tf32) weights
__device__ float g_wih0[2*GG*EE];
__device__ float g_wih1[2*GG*DD1];
__device__ float g_fc1 [2*HH*HH];
__device__ float g_fc2 [2*HH*HH];
__device__ float g_outw[2*HH*DD1];

// group-barrier state (4 groups of 32 CTAs; self-consistent across replays)
__device__ unsigned g_bc[128];
__device__ volatile unsigned g_bs[128];

__device__ __forceinline__ float cvt_tf32(float x) {
    uint32_t r;
    asm("cvt.rna.tf32.f32 %0, %1;" : "=r"(r) : "f"(x));
    return __uint_as_float(r);
}

__device__ __forceinline__ uint32_t smem_u32(const void* p) {
    uint32_t a;
    asm("{ .reg .u64 t; cvta.to.shared.u64 t, %1; cvt.u32.u64 %0, t; }" : "=r"(a) : "l"(p));
    return a;
}

__device__ __forceinline__ void cpasync16(uint32_t dst, const void* src) {
    asm volatile("cp.async.cg.shared.global [%0], [%1], 16;" :: "r"(dst), "l"(src));
}
#define CP_COMMIT() asm volatile("cp.async.commit_group;" ::: "memory")
#define CP_WAIT1()  asm volatile("cp.async.wait_group 1;" ::: "memory")

// ---------------- small elementwise kernels ----------------
__global__ void round_kernel(const float* __restrict__ src, float* __restrict__ dst, int n) {
    int i = blockIdx.x * blockDim.x + threadIdx.x;
    if (i < n) dst[i] = cvt_tf32(src[i]);
}

__global__ void embed_kernel(const int* __restrict__ i1, const int* __restrict__ i2,
                             const float* __restrict__ emb1, const float* __restrict__ emb2,
                             float* __restrict__ x0) {
    int idx = blockIdx.x * blockDim.x + threadIdx.x;
    if (idx >= SB * EE) return;
    int t = idx / EE, e = idx - t * EE;
    float v;
    if (e < 128) {
        v = emb1[(size_t)i1[t] * 128 + e];
    } else {
        int vi = i2[t];
        v = (vi == 0) ? 0.f : emb2[(size_t)vi * 64 + (e - 128)];
    }
    x0[idx] = cvt_tf32(v);
}

__global__ void dinv_kernel(const int* __restrict__ pg, float* __restrict__ dinv) {
    int row  = blockIdx.x * 8 + (threadIdx.x >> 5);
    int lane = threadIdx.x & 31;
    int b = row >> 8, s = row & 255;
    const int* ar = pg + ((size_t)b * 3 + 2) * (SS * SS) + (size_t)s * SS;
    int acc = 0;
    for (int t = lane; t < SS; t += 32) acc += ar[t];
    #pragma unroll
    for (int o = 16; o; o >>= 1) acc += __shfl_down_sync(0xffffffffu, acc, o);
    if (lane == 0) dinv[row] = rsqrtf((float)acc + 1.0f);
}

__global__ void an_kernel(const int* __restrict__ pg, const float* __restrict__ dinv,
                          float* __restrict__ an) {
    int idx = blockIdx.x * blockDim.x + threadIdx.x;
    if (idx >= BB * SS * SS) return;
    int t = idx & 255, s = (idx >> 8) & 255, b = idx >> 16;
    float a = (float)pg[((size_t)b * 3 + 2) * (SS * SS) + s * SS + t] + (s == t ? 1.f : 0.f);
    an[idx] = cvt_tf32(a * dinv[b * SS + s] * dinv[b * SS + t]);
}

__global__ void sumdir_kernel(const float* __restrict__ y, float* __restrict__ node) {
    int idx = blockIdx.x * blockDim.x + threadIdx.x;
    if (idx >= BB * SS * HH) return;
    int j = idx & 511, s = (idx >> 9) & 255, b = idx >> 17;
    size_t yi = ((size_t)s * BB + b) * DD1 + j;
    node[idx] = cvt_tf32(y[yi] + y[yi + HH]);
}

// [B,S,H] -> [B,H,S] (values already tf32-rounded at production)
__global__ void transpose_bsh(const float* __restrict__ src, float* __restrict__ dst) {
    __shared__ float t[32][33];
    int b = blockIdx.z;
    int s0 = blockIdx.y * 32, h0 = blockIdx.x * 32;
    src += (size_t)b * SS * HH;
    dst += (size_t)b * SS * HH;
    int x = threadIdx.x, y = threadIdx.y;
    #pragma unroll
    for (int i = 0; i < 32; i += 8) t[y + i][x] = src[(size_t)(s0 + y + i) * HH + h0 + x];
    __syncthreads();
    #pragma unroll
    for (int i = 0; i < 32; i += 8) dst[(size_t)(h0 + y + i) * SS + s0 + x] = t[x][y + i];
}

// ================= tf32 mma helpers =================
__device__ __forceinline__ void mma8(float* d, uint32_t a0, uint32_t a1, uint32_t a2,
                                     uint32_t a3, uint32_t b0, uint32_t b1) {
    asm volatile(
        "mma.sync.aligned.m16n8k8.row.col.f32.tf32.tf32.f32 "
        "{%0,%1,%2,%3}, {%4,%5,%6,%7}, {%8,%9}, {%0,%1,%2,%3};"
        : "+f"(d[0]), "+f"(d[1]), "+f"(d[2]), "+f"(d[3])
        : "r"(a0), "r"(a1), "r"(a2), "r"(a3), "r"(b0), "r"(b1));
}
#define FU(x) __float_as_uint(x)

// ============ tf32 mma.sync NT GEMM — operands pre-rounded, no mainloop cvt ========
// C[m,n] = sum_k A[m,k]*W[n,k] (+bias, +relu, +tf32-round for chained GEMMs).
template<bool RELU, bool TRANSOUT, bool ROUND>
__global__ void __launch_bounds__(256) mma_gemm_nt(
    const float* __restrict__ A, const float* __restrict__ A2,
    const float* __restrict__ W, const float* __restrict__ W2,
    const float* __restrict__ bias, const float* __restrict__ bias2,
    float* __restrict__ C, float* __restrict__ C2,
    int K, int K1, int Nsplit, int lda, int ldw, int ldc,
    long long sA, long long sW, long long sC)
{
    extern __shared__ float smg[];
    const int SLOT = 128 * PAD;

    int tid = threadIdx.x;
    int lane = tid & 31, warp = tid >> 5;
    int wm = warp >> 2, wn = warp & 3;
    int groupID = lane >> 2, tig = lane & 3;
    int n0 = blockIdx.x * 128, m0 = blockIdx.y * 128;
    if (W2 && n0 >= Nsplit) {
        W = W2; bias = bias2; C = C2; n0 -= Nsplit;
    }
    int z = blockIdx.z;
    A += (size_t)z * (size_t)sA;
    W += (size_t)z * (size_t)sW;
    C += (size_t)z * (size_t)sC;

    int lr = tid >> 2;
    int lc = (tid & 3) * 4;

    const int arb = wm * 64;
    const int wcb = wn * 32;

    uint32_t smb = smem_u32(smg);
    uint32_t dA0 = smb + (uint32_t)(lr * PAD + lc) * 4u;
    uint32_t dA1 = smb + (uint32_t)((lr + 64) * PAD + lc) * 4u;
    uint32_t dW0 = dA0 + (uint32_t)(NSTAGE * SLOT) * 4u;
    uint32_t dW1 = dA1 + (uint32_t)(NSTAGE * SLOT) * 4u;

    float acc[4][4][4];
    #pragma unroll
    for (int mt = 0; mt < 4; mt++)
        #pragma unroll
        for (int nt = 0; nt < 4; nt++)
            #pragma unroll
            for (int q = 0; q < 4; q++) acc[mt][nt][q] = 0.f;

    auto aload = [&](int c, int s) {
        int koff = c * 16 + lc;
        const float* Ab;
        if (A2 && koff >= K1)
            Ab = A2 + (size_t)(m0 + lr) * lda + (koff - K1);
        else
            Ab = A + (size_t)(m0 + lr) * lda + koff;
        const float* Wb = W + (size_t)(n0 + lr) * ldw + c * 16 + lc;
        uint32_t so = (uint32_t)(s * SLOT) * 4u;
        cpasync16(dA0 + so, Ab);
        cpasync16(dA1 + so, Ab + (size_t)64 * lda);
        cpasync16(dW0 + so, Wb);
        cpasync16(dW1 + so, Wb + (size_t)64 * ldw);
        CP_COMMIT();
    };

    int Cn = K >> 4;
    aload(0, 0);
    aload(1, 1);

    for (int c = 0; c < Cn; c++) {
        CP_WAIT1();
        __syncthreads();

        int slot = c % NSTAGE;
        if (c + 2 < Cn) aload(c + 2, (c + 2) % NSTAGE);

        const float* As = smg + slot * SLOT;
        const float* Ws = smg + (NSTAGE + slot) * SLOT;
        #pragma unroll
        for (int ks = 0; ks < 2; ks++) {
            int k0 = ks * 8;
            float af[4][4], bf[4][2];
            #pragma unroll
            for (int mt = 0; mt < 4; mt++) {
                int rb = arb + mt * 16 + groupID;
                af[mt][0] = As[rb * PAD + k0 + tig];
                af[mt][1] = As[(rb + 8) * PAD + k0 + tig];
                af[mt][2] = As[rb * PAD + k0 + 4 + tig];
                af[mt][3] = As[(rb + 8) * PAD + k0 + 4 + tig];
            }
            #pragma unroll
            for (int nt = 0; nt < 4; nt++) {
                int cb = wcb + nt * 8 + groupID;
                bf[nt][0] = Ws[cb * PAD + k0 + tig];
                bf[nt][1] = Ws[cb * PAD + k0 + 4 + tig];
            }
            #pragma unroll
            for (int mt = 0; mt < 4; mt++)
                #pragma unroll
                for (int nt = 0; nt < 4; nt++)
                    mma8(acc[mt][nt], FU(af[mt][0]), FU(af[mt][1]),
                         FU(af[mt][2]), FU(af[mt][3]),
                         FU(bf[nt][0]), FU(bf[nt][1]));
        }
    }

    #pragma unroll
    for (int mt = 0; mt < 4; mt++) {
        #pragma unroll
        for (int nt = 0; nt < 4; nt++) {
            int gr = m0 + arb + mt * 16 + groupID;
            int gc = n0 + wcb + nt * 8 + tig * 2;
            float b0 = 0.f, b1 = 0.f;
            if (bias) { b0 = bias[gc]; b1 = bias[gc + 1]; }
            float v00 = acc[mt][nt][0] + b0, v01 = acc[mt][nt][1] + b1;
            float v10 = acc[mt][nt][2] + b0, v11 = acc[mt][nt][3] + b1;
            if (RELU) {
                v00 = fmaxf(v00, 0.f); v01 = fmaxf(v01, 0.f);
                v10 = fmaxf(v10, 0.f); v11 = fmaxf(v11, 0.f);
            }
            if (ROUND) {
                v00 = cvt_tf32(v00); v01 = cvt_tf32(v01);
                v10 = cvt_tf32(v10); v11 = cvt_tf32(v11);
            }
            size_t i0, i1;
            if (TRANSOUT) {
                int b_  = gr >> 8, s_ = gr & 255;
                int b2_ = (gr + 8) >> 8, s2_ = (gr + 8) & 255;
                i0 = ((size_t)s_  * BB + b_ ) * ldc + gc;
                i1 = ((size_t)s2_ * BB + b2_) * ldc + gc;
            } else {
                i0 = (size_t)gr * ldc + gc;
                i1 = (size_t)(gr + 8) * ldc + gc;
            }
            *(float2*)&C[i0] = make_float2(v00, v01);
            *(float2*)&C[i1] = make_float2(v10, v11);
        }
    }
}

// ================= persistent GRU: single-term tf32 (R14-proven) =================
#define GRU_SMEM 124416

__device__ __forceinline__ void group_barrier(int g, unsigned* ls) {
    __syncthreads();
    if (threadIdx.x == 0) {
        unsigned s = (*ls) ^ 1u;
        __threadfence();
        unsigned old = atomicAdd(&g_bc[g * 32], 1u);
        if (old == 31u) {
            *(volatile unsigned*)&g_bc[g * 32] = 0u;
            __threadfence();
            g_bs[g * 32] = s;
        } else {
            while (g_bs[g * 32] != s) { }
        }
        __threadfence();
        *ls = s;
    }
    __syncthreads();
}

__global__ void __launch_bounds__(768, 1) gru_persistent(
    const float* __restrict__ xgf, const float* __restrict__ xgb,
    const float* __restrict__ whhf, const float* __restrict__ whhb,
    const float* __restrict__ bhhf, const float* __restrict__ bhhb,
    float* hA, float* hB,
    float* __restrict__ y, float* __restrict__ hid_out)
{
    extern __shared__ float sm[];
    float* Wsm   = sm;
    float* Abuf0 = sm + 24576;
    float* Abuf1 = sm + 24576 + 2048;
    float* sg    = sm + 24576;

    int tid = threadIdx.x;
    int lane = tid & 31, warp = tid >> 5;
    int gid = lane >> 2, tig = lane & 3;
    int kh = warp / 12;
    int inner = warp - kh * 12;
    int rw = inner & 3, gw = inner >> 2;

    int bid = blockIdx.x;
    int ct = bid & 31, rt = (bid >> 5) & 1, dir = bid >> 6;
    int grp = bid >> 5;
    const float* Wsrc = dir ? whhb : whhf;
    const float* bhh  = dir ? bhhb : bhhf;
    const float* xg   = dir ? xgb  : xgf;
    const int rowbase = dir * BB + rt * 64;
    const int sxa = gid * 4;

    unsigned ls = g_bs[grp * 32];

    for (int i = tid; i < 48 * 128; i += 768) {
        int lr = i >> 7;
        int q  = i & 127;
        int g = lr >> 4, j = lr & 15;
        float4 v = *(const float4*)(Wsrc + ((size_t)(g * HH + ct * 16 + j)) * HH + q * 4);
        int kk = q * 4;
        int w = (kk & ~31) + ((kk & 31) ^ ((lr & 7) * 4));
        *(float4*)&Wsm[lr * HH + w] =
            make_float4(cvt_tf32(v.x), cvt_tf32(v.y), cvt_tf32(v.z), cvt_tf32(v.w));
    }
    __syncthreads();

    for (int t = 0; t < SS; t++) {
        const float* src = (t & 1) ? hB : hA;
        float*       dst = (t & 1) ? hA : hB;
        int tt = dir ? (SS - 1 - t) : t;
        const float* hs = src + (size_t)rowbase * HH;

        float acc[2][4];
        #pragma unroll
        for (int nt = 0; nt < 2; nt++)
            #pragma unroll
            for (int q = 0; q < 4; q++) acc[nt][q] = 0.f;

        for (int L = tid; L < 1024; L += 768) {
            int ch = L >> 9;
            int i = L & 511;
            int r = i >> 3, q = i & 7;
            float4 v = __ldcg((const float4*)(hs + (size_t)r * HH + ch * 32 + q * 4));
            int kk = q * 4;
            int w = kk ^ ((r & 7) * 4);
            float* row = (ch ? Abuf1 : Abuf0) + r * 32;
            *(float4*)&row[w] =
                make_float4(cvt_tf32(v.x), cvt_tf32(v.y), cvt_tf32(v.z), cvt_tf32(v.w));
        }
        __syncthreads();

        const float* Ab = kh ? Abuf1 : Abuf0;
        const int arow = rw * 16 + gid;

        for (int it = 0; it < 8; it++) {
            bool hasNext = (it + 1 < 8);
            float4 pf0, pf1;
            int r0 = 0, q0 = 0, c0 = 0, r1 = 0, q1 = 0, c1 = 0;
            bool hv1 = false;
            if (hasNext) {
                int base = (it + 1) * 2;
                int L = tid;
                c0 = base + (L >> 9); { int i = L & 511; r0 = i >> 3; q0 = i & 7; }
                pf0 = __ldcg((const float4*)(hs + (size_t)r0 * HH + c0 * 32 + q0 * 4));
                int L2 = tid + 768;
                if (L2 < 1024) {
                    c1 = base + (L2 >> 9); { int i = L2 & 511; r1 = i >> 3; q1 = i & 7; }
                    pf1 = __ldcg((const float4*)(hs + (size_t)r1 * HH + c1 * 32 + q1 * 4));
                    hv1 = true;
                }
            }

            int cc = it * 2 + kh;
            #pragma unroll
            for (int ck = 0; ck < 4; ck++) {
                int k8 = ck * 8;
                float a0 = Ab[arow * 32 + ((k8 + tig) ^ sxa)];
                float a1 = Ab[(arow + 8) * 32 + ((k8 + tig) ^ sxa)];
                float a2 = Ab[arow * 32 + ((k8 + 4 + tig) ^ sxa)];
                float a3 = Ab[(arow + 8) * 32 + ((k8 + 4 + tig) ^ sxa)];
                #pragma unroll
                for (int nt = 0; nt < 2; nt++) {
                    int wr = gw * 16 + nt * 8 + gid;
                    const float* Wb = Wsm + (size_t)wr * HH + cc * 32;
                    float b0 = Wb[(k8 + tig) ^ sxa];
                    float b1 = Wb[(k8 + 4 + tig) ^ sxa];
                    mma8(acc[nt], FU(a0), FU(a1), FU(a2), FU(a3), FU(b0), FU(b1));
                }
            }
            __syncthreads();

            if (hasNext) {
                {
                    float4 v = pf0;
                    int kk = q0 * 4;
                    int w = kk ^ ((r0 & 7) * 4);
                    float* row = ((c0 & 1) ? Abuf1 : Abuf0) + r0 * 32;
                    *(float4*)&row[w] =
                        make_float4(cvt_tf32(v.x), cvt_tf32(v.y), cvt_tf32(v.z), cvt_tf32(v.w));
                }
                if (hv1) {
                    float4 v = pf1;
                    int kk = q1 * 4;
                    int w = kk ^ ((r1 & 7) * 4);
                    float* row = ((c1 & 1) ? Abuf1 : Abuf0) + r1 * 32;
                    *(float4*)&row[w] =
                        make_float4(cvt_tf32(v.x), cvt_tf32(v.y), cvt_tf32(v.z), cvt_tf32(v.w));
                }
                __syncthreads();
            }
        }

        {
            float* sgp = sg + ((size_t)kh * 3 + gw) * 64 * 17;
            #pragma unroll
            for (int nt = 0; nt < 2; nt++) {
                int col = nt * 8 + tig * 2;
                sgp[arow * 17 + col]     = acc[nt][0];
                sgp[arow * 17 + col + 1] = acc[nt][1];
                sgp[(arow + 8) * 17 + col]     = acc[nt][2];
                sgp[(arow + 8) * 17 + col + 1] = acc[nt][3];
            }
        }
        __syncthreads();

        for (int i = tid; i < 1024; i += 768) {
            int row = i >> 4, col = i & 15;
            int bidx = rt * 64 + row;
            int gcol = ct * 16 + col;
            float hr = sg[0 * 64 * 17 + row * 17 + col] + sg[(3 + 0) * 64 * 17 + row * 17 + col] + bhh[gcol];
            float hz = sg[1 * 64 * 17 + row * 17 + col] + sg[(3 + 1) * 64 * 17 + row * 17 + col] + bhh[HH + gcol];
            float hn = sg[2 * 64 * 17 + row * 17 + col] + sg[(3 + 2) * 64 * 17 + row * 17 + col] + bhh[2 * HH + gcol];
            const float* xrow = xg + ((size_t)tt * BB + bidx) * GG;
            float xr = xrow[gcol], xz = xrow[HH + gcol], xn = xrow[2 * HH + gcol];
            float hp = __ldcg(src + (size_t)(rowbase + row) * HH + gcol);
            float rr = 1.f / (1.f + expf(-(xr + hr)));
            float zz = 1.f / (1.f + expf(-(xz + hz)));
            float nn = tanhf(xn + rr * hn);
            float hnew = (1.f - zz) * nn + zz * hp;
            dst[(size_t)(rowbase + row) * HH + gcol] = hnew;
            // y feeds only GEMM A / sumdir->GEMM inputs: pre-round to tf32
            y[((size_t)tt * BB + bidx) * DD1 + dir * HH + gcol] = cvt_tf32(hnew);
            if (t == SS - 1)
                hid_out[((size_t)dir * BB + bidx) * HH + gcol] = hnew;  // exact output
        }

        if (t < SS - 1) group_barrier(grp, &ls);
    }
}

// ---------------- host orchestration ----------------
extern "C" void kernel_launch(void* const* d_in, const int* in_sizes, int n_in,
                              void* d_out, int out_size) {
    const int*   i1    = (const int*)d_in[0];
    const int*   i2    = (const int*)d_in[1];
    const int*   pg    = (const int*)d_in[3];
    const float* emb1  = (const float*)d_in[4];
    const float* emb2  = (const float*)d_in[5];
    const float* wih0f = (const float*)d_in[6];
    const float* whh0f = (const float*)d_in[7];
    const float* bih0f = (const float*)d_in[8];
    const float* bhh0f = (const float*)d_in[9];
    const float* wih0b = (const float*)d_in[10];
    const float* whh0b = (const float*)d_in[11];
    const float* bih0b = (const float*)d_in[12];
    const float* bhh0b = (const float*)d_in[13];
    const float* wih1f = (const float*)d_in[14];
    const float* whh1f = (const float*)d_in[15];
    const float* bih1f = (const float*)d_in[16];
    const float* bhh1f = (const float*)d_in[17];
    const float* wih1b = (const float*)d_in[18];
    const float* whh1b = (const float*)d_in[19];
    const float* bih1b = (const float*)d_in[20];
    const float* bhh1b = (const float*)d_in[21];
    const float* fc1w  = (const float*)d_in[22];
    const float* fc1b  = (const float*)d_in[23];
    const float* fc2w  = (const float*)d_in[24];
    const float* fc2b  = (const float*)d_in[25];
    const float* outw  = (const float*)d_in[26];
    const float* outb  = (const float*)d_in[27];
    float* out = (float*)d_out;

    float *x0, *xgf, *xgb, *y0, *y1, *h0, *h1, *an, *dinv, *node, *node2, *ni, *tmp, *nodeT;
    float *rwih0, *rwih1, *rfc1, *rfc2, *routw;
    cudaGetSymbolAddress((void**)&x0,   g_x0);
    cudaGetSymbolAddress((void**)&xgf,  g_xgf);
    cudaGetSymbolAddress((void**)&xgb,  g_xgb);
    cudaGetSymbolAddress((void**)&y0,   g_y0);
    cudaGetSymbolAddress((void**)&y1,   g_y1);
    cudaGetSymbolAddress((void**)&h0,   g_h0);
    cudaGetSymbolAddress((void**)&h1,   g_h1);
    cudaGetSymbolAddress((void**)&an,   g_an);
    cudaGetSymbolAddress((void**)&dinv, g_dinv);
    cudaGetSymbolAddress((void**)&node, g_node);
    cudaGetSymbolAddress((void**)&node2,g_node2);
    cudaGetSymbolAddress((void**)&ni,   g_ni);
    cudaGetSymbolAddress((void**)&tmp,  g_tmp);
    cudaGetSymbolAddress((void**)&nodeT,g_nodeT);
    cudaGetSymbolAddress((void**)&rwih0,g_wih0);
    cudaGetSymbolAddress((void**)&rwih1,g_wih1);
    cudaGetSymbolAddress((void**)&rfc1, g_fc1);
    cudaGetSymbolAddress((void**)&rfc2, g_fc2);
    cudaGetSymbolAddress((void**)&routw,g_outw);

    cudaFuncSetAttribute(gru_persistent,
                         cudaFuncAttributeMaxDynamicSharedMemorySize, GRU_SMEM);
    cudaFuncSetAttribute(mma_gemm_nt<false,false,true>,
                         cudaFuncAttributeMaxDynamicSharedMemorySize, GEMM_SMEM);
    cudaFuncSetAttribute(mma_gemm_nt<true,false,true>,
                         cudaFuncAttributeMaxDynamicSharedMemorySize, GEMM_SMEM);
    cudaFuncSetAttribute(mma_gemm_nt<true,true,false>,
                         cudaFuncAttributeMaxDynamicSharedMemorySize, GEMM_SMEM);

    float* hid_base = out + (size_t)SB * HH;

    // 0) pre-round weights to tf32 (RNA) once per launch
    round_kernel<<<(GG*EE + 255)/256, 256>>>(wih0f, rwih0, GG*EE);
    round_kernel<<<(GG*EE + 255)/256, 256>>>(wih0b, rwih0 + (size_t)GG*EE, GG*EE);
    round_kernel<<<(GG*DD1 + 255)/256, 256>>>(wih1f, rwih1, GG*DD1);
    round_kernel<<<(GG*DD1 + 255)/256, 256>>>(wih1b, rwih1 + (size_t)GG*DD1, GG*DD1);
    round_kernel<<<(2*HH*HH + 255)/256, 256>>>(fc1w, rfc1, 2*HH*HH);
    round_kernel<<<(2*HH*HH + 255)/256, 256>>>(fc2w, rfc2, 2*HH*HH);
    round_kernel<<<(2*HH*DD1 + 255)/256, 256>>>(outw, routw, 2*HH*DD1);

    // 1) embedding (tf32-rounded)
    embed_kernel<<<(SB * EE + 255) / 256, 256>>>(i1, i2, emb1, emb2, x0);

    // 2) layer0 input gates (fused f+b, N=3072); output rounded for GRU use
    dim3 gG2(2 * GG / 128, SB / 128, 1);
    mma_gemm_nt<false,false,true><<<gG2, 256, GEMM_SMEM>>>(
        x0, nullptr, rwih0, rwih0 + (size_t)GG*EE, bih0f, bih0b,
        xgf, xgb, EE, 0, GG, EE, EE, GG, 0, 0, 0);

    // 3) layer0 recurrence (persistent)
    cudaMemsetAsync(h0, 0, (size_t)2 * BB * HH * sizeof(float));
    gru_persistent<<<128, 768, GRU_SMEM>>>(xgf, xgb, whh0f, whh0b, bhh0f, bhh0b,
                                           h0, h1, y0, hid_base);

    // 4) layer1 input gates (fused f+b); y0 already tf32-rounded
    mma_gemm_nt<false,false,true><<<gG2, 256, GEMM_SMEM>>>(
        y0, nullptr, rwih1, rwih1 + (size_t)GG*DD1, bih1f, bih1b,
        xgf, xgb, DD1, 0, GG, DD1, DD1, GG, 0, 0, 0);

    // 5) layer1 recurrence
    cudaMemsetAsync(h0, 0, (size_t)2 * BB * HH * sizeof(float));
    gru_persistent<<<128, 768, GRU_SMEM>>>(xgf, xgb, whh1f, whh1b, bhh1f, bhh1b,
                                           h0, h1, y1, hid_base + 2 * BB * HH);

    // 6) direction sum -> node [B,S,H] (rounded)
    sumdir_kernel<<<(BB * SS * HH + 255) / 256, 256>>>(y1, node);

    // 7) normalized adjacency (rounded)
    dinv_kernel<<<BB * SS / 8, 256>>>(pg, dinv);
    an_kernel<<<(BB * SS * SS + 255) / 256, 256>>>(pg, dinv, an);

    // 8) GNN hops
    dim3 gH(HH / 128, SB / 128, 1);
    dim3 gAn(HH / 128, SS / 128, BB);
    dim3 gT(HH / 32, SS / 32, BB);
    float* cur = node; float* nxt = node2;
    for (int i = 0; i < 2; i++) {
        const float* f1w = rfc1 + (size_t)i * HH * HH;
        const float* f1b = fc1b + (size_t)i * HH;
        const float* f2w = rfc2 + (size_t)i * HH * HH;
        const float* f2b = fc2b + (size_t)i * HH;
        const float* ow  = routw + (size_t)i * HH * DD1;
        const float* ob  = outb + (size_t)i * HH;

        transpose_bsh<<<gT, dim3(32, 8)>>>(cur, nodeT);
        mma_gemm_nt<false,false,true><<<gAn, 256, GEMM_SMEM>>>(
            an, nullptr, nodeT, nullptr, nullptr, nullptr, tmp, nullptr,
            SS, 0, 0, SS, SS, HH,
            (long long)SS * SS, (long long)HH * SS, (long long)SS * HH);
        mma_gemm_nt<true,false,true><<<gH, 256, GEMM_SMEM>>>(
            tmp, nullptr, f1w, nullptr, f1b, nullptr, ni, nullptr,
            HH, 0, 0, HH, HH, HH, 0, 0, 0);

        transpose_bsh<<<gT, dim3(32, 8)>>>(ni, nodeT);
        mma_gemm_nt<false,false,true><<<gAn, 256, GEMM_SMEM>>>(
            an, nullptr, nodeT, nullptr, nullptr, nullptr, tmp, nullptr,
            SS, 0, 0, SS, SS, HH,
            (long long)SS * SS, (long long)HH * SS, (long long)SS * HH);
        mma_gemm_nt<true,false,true><<<gH, 256, GEMM_SMEM>>>(
            tmp, nullptr, f2w, nullptr, f2b, nullptr, ni, nullptr,
            HH, 0, 0, HH, HH, HH, 0, 0, 0);

        // fused: out = relu([cur|ni] @ ow^T + ob), K=1024, split at 512
        if (i == 0) {
            mma_gemm_nt<true,false,true><<<gH, 256, GEMM_SMEM>>>(
                cur, ni, ow, nullptr, ob, nullptr, nxt, nullptr,
                DD1, HH, 0, HH, DD1, HH, 0, 0, 0);
            float* tptr = cur; cur = nxt; nxt = tptr;
        } else {
            // final hop: write pade_outputs [S,B,H] directly, exact fp32
            mma_gemm_nt<true,true,false><<<gH, 256, GEMM_SMEM>>>(
                cur, ni, ow, nullptr, ob, nullptr, out, nullptr,
                DD1, HH, 0, HH, DD1, HH, 0, 0, 0);
        }
    }
}

// round 16
// speedup vs baseline: 1.5802x; 1.1219x over previous
#include <cuda_runtime.h>
#include <math.h>
#include <stdint.h>

#define SS 256
#define BB 128
#define HH 512
#define GG 1536
#define EE 192
#define DD1 1024
#define SB (SS*BB)   // 32768
#define PAD 20       // smem row stride in floats (conflict-free: 20r mod 32 distinct)
#define NSTAGE 3
#define GEMM_SMEM (2 * NSTAGE * 128 * PAD * 4)   // 61440 B

// ---------------- scratch (__device__ globals, no allocation) ----------------
__device__ float g_x0 [SB*EE];
__device__ float g_xgf[SB*GG];
__device__ float g_xgb[SB*GG];
__device__ float g_y0 [SB*DD1];
__device__ float g_y1 [SB*DD1];
__device__ float g_h0 [2*BB*HH];
__device__ float g_h1 [2*BB*HH];
__device__ float g_an [BB*SS*SS];
__device__ float g_dinv[BB*SS];
__device__ float g_node [BB*SS*HH];
__device__ float g_node2[BB*SS*HH];
__device__ float g_ni   [BB*SS*HH];
__device__ float g_tmp  [BB*SS*HH];
__device__ float g_nodeT[BB*HH*SS];
// pre-rounded (tf32) weights
__device__ float g_wih0[2*GG*EE];
__device__ float g_wih1[2*GG*DD1];
__device__ float g_fc1 [2*HH*HH];
__device__ float g_fc2 [2*HH*HH];
__device__ float g_outw[2*HH*DD1];

// group-barrier state (4 groups of 32 CTAs; self-consistent across replays)
__device__ unsigned g_bc[128];
__device__ volatile unsigned g_bs[128];

__device__ __forceinline__ float cvt_tf32(float x) {
    uint32_t r;
    asm("cvt.rna.tf32.f32 %0, %1;" : "=r"(r) : "f"(x));
    return __uint_as_float(r);
}

__device__ __forceinline__ uint32_t smem_u32(const void* p) {
    uint32_t a;
    asm("{ .reg .u64 t; cvta.to.shared.u64 t, %1; cvt.u32.u64 %0, t; }" : "=r"(a) : "l"(p));
    return a;
}

__device__ __forceinline__ void cpasync16(uint32_t dst, const void* src) {
    asm volatile("cp.async.cg.shared.global [%0], [%1], 16;" :: "r"(dst), "l"(src));
}
#define CP_COMMIT() asm volatile("cp.async.commit_group;" ::: "memory")
#define CP_WAIT1()  asm volatile("cp.async.wait_group 1;" ::: "memory")

// ---------------- small elementwise kernels ----------------
__global__ void round_kernel(const float* __restrict__ src, float* __restrict__ dst, int n) {
    int i = blockIdx.x * blockDim.x + threadIdx.x;
    if (i < n) dst[i] = cvt_tf32(src[i]);
}

__global__ void embed_kernel(const int* __restrict__ i1, const int* __restrict__ i2,
                             const float* __restrict__ emb1, const float* __restrict__ emb2,
                             float* __restrict__ x0) {
    int idx = blockIdx.x * blockDim.x + threadIdx.x;
    if (idx >= SB * EE) return;
    int t = idx / EE, e = idx - t * EE;
    float v;
    if (e < 128) {
        v = emb1[(size_t)i1[t] * 128 + e];
    } else {
        int vi = i2[t];
        v = (vi == 0) ? 0.f : emb2[(size_t)vi * 64 + (e - 128)];
    }
    x0[idx] = cvt_tf32(v);
}

__global__ void dinv_kernel(const int* __restrict__ pg, float* __restrict__ dinv) {
    int row  = blockIdx.x * 8 + (threadIdx.x >> 5);
    int lane = threadIdx.x & 31;
    int b = row >> 8, s = row & 255;
    const int* ar = pg + ((size_t)b * 3 + 2) * (SS * SS) + (size_t)s * SS;
    int acc = 0;
    for (int t = lane; t < SS; t += 32) acc += ar[t];
    #pragma unroll
    for (int o = 16; o; o >>= 1) acc += __shfl_down_sync(0xffffffffu, acc, o);
    if (lane == 0) dinv[row] = rsqrtf((float)acc + 1.0f);
}

__global__ void an_kernel(const int* __restrict__ pg, const float* __restrict__ dinv,
                          float* __restrict__ an) {
    int idx = blockIdx.x * blockDim.x + threadIdx.x;
    if (idx >= BB * SS * SS) return;
    int t = idx & 255, s = (idx >> 8) & 255, b = idx >> 16;
    float a = (float)pg[((size_t)b * 3 + 2) * (SS * SS) + s * SS + t] + (s == t ? 1.f : 0.f);
    an[idx] = cvt_tf32(a * dinv[b * SS + s] * dinv[b * SS + t]);
}

__global__ void sumdir_kernel(const float* __restrict__ y, float* __restrict__ node) {
    int idx = blockIdx.x * blockDim.x + threadIdx.x;
    if (idx >= BB * SS * HH) return;
    int j = idx & 511, s = (idx >> 9) & 255, b = idx >> 17;
    size_t yi = ((size_t)s * BB + b) * DD1 + j;
    node[idx] = cvt_tf32(y[yi] + y[yi + HH]);
}

// [B,S,H] -> [B,H,S]
__global__ void transpose_bsh(const float* __restrict__ src, float* __restrict__ dst) {
    __shared__ float t[32][33];
    int b = blockIdx.z;
    int s0 = blockIdx.y * 32, h0 = blockIdx.x * 32;
    src += (size_t)b * SS * HH;
    dst += (size_t)b * SS * HH;
    int x = threadIdx.x, y = threadIdx.y;
    #pragma unroll
    for (int i = 0; i < 32; i += 8) t[y + i][x] = src[(size_t)(s0 + y + i) * HH + h0 + x];
    __syncthreads();
    #pragma unroll
    for (int i = 0; i < 32; i += 8) dst[(size_t)(h0 + y + i) * SS + s0 + x] = t[x][y + i];
}

// ================= tf32 mma helpers =================
__device__ __forceinline__ void mma8(float* d, uint32_t a0, uint32_t a1, uint32_t a2,
                                     uint32_t a3, uint32_t b0, uint32_t b1) {
    asm volatile(
        "mma.sync.aligned.m16n8k8.row.col.f32.tf32.tf32.f32 "
        "{%0,%1,%2,%3}, {%4,%5,%6,%7}, {%8,%9}, {%0,%1,%2,%3};"
        : "+f"(d[0]), "+f"(d[1]), "+f"(d[2]), "+f"(d[3])
        : "r"(a0), "r"(a1), "r"(a2), "r"(a3), "r"(b0), "r"(b1));
}
#define FU(x) __float_as_uint(x)

// ============ tf32 mma.sync NT GEMM — R15-proven (pre-rounded operands) ========
template<bool RELU, bool TRANSOUT, bool ROUND>
__global__ void __launch_bounds__(256) mma_gemm_nt(
    const float* __restrict__ A, const float* __restrict__ A2,
    const float* __restrict__ W, const float* __restrict__ W2,
    const float* __restrict__ bias, const float* __restrict__ bias2,
    float* __restrict__ C, float* __restrict__ C2,
    int K, int K1, int Nsplit, int lda, int ldw, int ldc,
    long long sA, long long sW, long long sC)
{
    extern __shared__ float smg[];
    const int SLOT = 128 * PAD;

    int tid = threadIdx.x;
    int lane = tid & 31, warp = tid >> 5;
    int wm = warp >> 2, wn = warp & 3;
    int groupID = lane >> 2, tig = lane & 3;
    int n0 = blockIdx.x * 128, m0 = blockIdx.y * 128;
    if (W2 && n0 >= Nsplit) {
        W = W2; bias = bias2; C = C2; n0 -= Nsplit;
    }
    int z = blockIdx.z;
    A += (size_t)z * (size_t)sA;
    W += (size_t)z * (size_t)sW;
    C += (size_t)z * (size_t)sC;

    int lr = tid >> 2;
    int lc = (tid & 3) * 4;

    const int arb = wm * 64;
    const int wcb = wn * 32;

    uint32_t smb = smem_u32(smg);
    uint32_t dA0 = smb + (uint32_t)(lr * PAD + lc) * 4u;
    uint32_t dA1 = smb + (uint32_t)((lr + 64) * PAD + lc) * 4u;
    uint32_t dW0 = dA0 + (uint32_t)(NSTAGE * SLOT) * 4u;
    uint32_t dW1 = dA1 + (uint32_t)(NSTAGE * SLOT) * 4u;

    float acc[4][4][4];
    #pragma unroll
    for (int mt = 0; mt < 4; mt++)
        #pragma unroll
        for (int nt = 0; nt < 4; nt++)
            #pragma unroll
            for (int q = 0; q < 4; q++) acc[mt][nt][q] = 0.f;

    auto aload = [&](int c, int s) {
        int koff = c * 16 + lc;
        const float* Ab;
        if (A2 && koff >= K1)
            Ab = A2 + (size_t)(m0 + lr) * lda + (koff - K1);
        else
            Ab = A + (size_t)(m0 + lr) * lda + koff;
        const float* Wb = W + (size_t)(n0 + lr) * ldw + c * 16 + lc;
        uint32_t so = (uint32_t)(s * SLOT) * 4u;
        cpasync16(dA0 + so, Ab);
        cpasync16(dA1 + so, Ab + (size_t)64 * lda);
        cpasync16(dW0 + so, Wb);
        cpasync16(dW1 + so, Wb + (size_t)64 * ldw);
        CP_COMMIT();
    };

    int Cn = K >> 4;
    aload(0, 0);
    aload(1, 1);

    for (int c = 0; c < Cn; c++) {
        CP_WAIT1();
        __syncthreads();

        int slot = c % NSTAGE;
        if (c + 2 < Cn) aload(c + 2, (c + 2) % NSTAGE);

        const float* As = smg + slot * SLOT;
        const float* Ws = smg + (NSTAGE + slot) * SLOT;
        #pragma unroll
        for (int ks = 0; ks < 2; ks++) {
            int k0 = ks * 8;
            float af[4][4], bf[4][2];
            #pragma unroll
            for (int mt = 0; mt < 4; mt++) {
                int rb = arb + mt * 16 + groupID;
                af[mt][0] = As[rb * PAD + k0 + tig];
                af[mt][1] = As[(rb + 8) * PAD + k0 + tig];
                af[mt][2] = As[rb * PAD + k0 + 4 + tig];
                af[mt][3] = As[(rb + 8) * PAD + k0 + 4 + tig];
            }
            #pragma unroll
            for (int nt = 0; nt < 4; nt++) {
                int cb = wcb + nt * 8 + groupID;
                bf[nt][0] = Ws[cb * PAD + k0 + tig];
                bf[nt][1] = Ws[cb * PAD + k0 + 4 + tig];
            }
            #pragma unroll
            for (int mt = 0; mt < 4; mt++)
                #pragma unroll
                for (int nt = 0; nt < 4; nt++)
                    mma8(acc[mt][nt], FU(af[mt][0]), FU(af[mt][1]),
                         FU(af[mt][2]), FU(af[mt][3]),
                         FU(bf[nt][0]), FU(bf[nt][1]));
        }
    }

    #pragma unroll
    for (int mt = 0; mt < 4; mt++) {
        #pragma unroll
        for (int nt = 0; nt < 4; nt++) {
            int gr = m0 + arb + mt * 16 + groupID;
            int gc = n0 + wcb + nt * 8 + tig * 2;
            float b0 = 0.f, b1 = 0.f;
            if (bias) { b0 = bias[gc]; b1 = bias[gc + 1]; }
            float v00 = acc[mt][nt][0] + b0, v01 = acc[mt][nt][1] + b1;
            float v10 = acc[mt][nt][2] + b0, v11 = acc[mt][nt][3] + b1;
            if (RELU) {
                v00 = fmaxf(v00, 0.f); v01 = fmaxf(v01, 0.f);
                v10 = fmaxf(v10, 0.f); v11 = fmaxf(v11, 0.f);
            }
            if (ROUND) {
                v00 = cvt_tf32(v00); v01 = cvt_tf32(v01);
                v10 = cvt_tf32(v10); v11 = cvt_tf32(v11);
            }
            size_t i0, i1;
            if (TRANSOUT) {
                int b_  = gr >> 8, s_ = gr & 255;
                int b2_ = (gr + 8) >> 8, s2_ = (gr + 8) & 255;
                i0 = ((size_t)s_  * BB + b_ ) * ldc + gc;
                i1 = ((size_t)s2_ * BB + b2_) * ldc + gc;
            } else {
                i0 = (size_t)gr * ldc + gc;
                i1 = (size_t)(gr + 8) * ldc + gc;
            }
            *(float2*)&C[i0] = make_float2(v00, v01);
            *(float2*)&C[i1] = make_float2(v10, v11);
        }
    }
}

// ================= persistent GRU: single-term tf32, single-stage step =================
// Wsm: [48][512] float hi (98304 B); Ah: [64][512] float hi (131072 B) = 229376 B total.
// sg epilogue overlay on Ah. Per step: 1 bulk stage + 1 sync + all MMAs + 2 syncs.
#define GRU_SMEM 229376

__device__ __forceinline__ void group_barrier(int g, unsigned* ls) {
    __syncthreads();
    if (threadIdx.x == 0) {
        unsigned s = (*ls) ^ 1u;
        __threadfence();
        unsigned old = atomicAdd(&g_bc[g * 32], 1u);
        if (old == 31u) {
            *(volatile unsigned*)&g_bc[g * 32] = 0u;
            __threadfence();
            g_bs[g * 32] = s;
        } else {
            while (g_bs[g * 32] != s) { }
        }
        __threadfence();
        *ls = s;
    }
    __syncthreads();
}

__global__ void __launch_bounds__(768, 1) gru_persistent(
    const float* __restrict__ xgf, const float* __restrict__ xgb,
    const float* __restrict__ whhf, const float* __restrict__ whhb,
    const float* __restrict__ bhhf, const float* __restrict__ bhhb,
    float* hA, float* hB,
    float* __restrict__ y, float* __restrict__ hid_out)
{
    extern __shared__ float sm[];
    float* Wsm = sm;                 // [48][512] hi, swizzled per 32-chunk
    float* Ah  = sm + 24576;         // [64][512] hi, swizzled per 32-chunk
    float* sg  = sm + 24576;         // epilogue overlay [2][3][64][17]

    int tid = threadIdx.x;
    int lane = tid & 31, warp = tid >> 5;
    int gid = lane >> 2, tig = lane & 3;
    int kh = warp / 12;
    int inner = warp - kh * 12;
    int rw = inner & 3, gw = inner >> 2;

    int bid = blockIdx.x;
    int ct = bid & 31, rt = (bid >> 5) & 1, dir = bid >> 6;
    int grp = bid >> 5;
    const float* Wsrc = dir ? whhb : whhf;
    const float* bhh  = dir ? bhhb : bhhf;
    const float* xg   = dir ? xgb  : xgf;
    const int rowbase = dir * BB + rt * 64;
    const int sxa = gid * 4;

    unsigned ls = g_bs[grp * 32];

    // preload weights (tf32 hi only), swizzled per 32-chunk
    for (int i = tid; i < 48 * 128; i += 768) {
        int lr = i >> 7;
        int q  = i & 127;
        int g = lr >> 4, j = lr & 15;
        float4 v = *(const float4*)(Wsrc + ((size_t)(g * HH + ct * 16 + j)) * HH + q * 4);
        int kk = q * 4;
        int w = (kk & ~31) + ((kk & 31) ^ ((lr & 7) * 4));
        *(float4*)&Wsm[lr * HH + w] =
            make_float4(cvt_tf32(v.x), cvt_tf32(v.y), cvt_tf32(v.z), cvt_tf32(v.w));
    }
    __syncthreads();

    for (int t = 0; t < SS; t++) {
        const float* src = (t & 1) ? hB : hA;
        float*       dst = (t & 1) ? hA : hB;
        int tt = dir ? (SS - 1 - t) : t;
        const float* hs = src + (size_t)rowbase * HH;

        float acc[2][4];
        #pragma unroll
        for (int nt = 0; nt < 2; nt++)
            #pragma unroll
            for (int q = 0; q < 4; q++) acc[nt][q] = 0.f;

        // ---- single bulk stage: all 64x512 of h (8192 float4) ----
        #pragma unroll 4
        for (int i = tid; i < 8192; i += 768) {
            int r = i >> 7;            // 0..63
            int q = i & 127;           // float4 index within row
            float4 v = __ldcg((const float4*)(hs + (size_t)r * HH + q * 4));
            int kk = q * 4;
            int w = (kk & ~31) + ((kk & 31) ^ ((r & 7) * 4));
            *(float4*)&Ah[r * HH + w] =
                make_float4(cvt_tf32(v.x), cvt_tf32(v.y), cvt_tf32(v.z), cvt_tf32(v.w));
        }
        __syncthreads();

        // ---- all MMAs, no intervening barriers ----
        const int arow = rw * 16 + gid;
        #pragma unroll
        for (int it = 0; it < 8; it++) {
            int cc = it * 2 + kh;
            const float* Arow0 = Ah + (size_t)arow * HH + cc * 32;
            const float* Arow1 = Ah + (size_t)(arow + 8) * HH + cc * 32;
            #pragma unroll
            for (int ck = 0; ck < 4; ck++) {
                int k8 = ck * 8;
                float a0 = Arow0[(k8 + tig) ^ sxa];
                float a1 = Arow1[(k8 + tig) ^ sxa];
                float a2 = Arow0[(k8 + 4 + tig) ^ sxa];
                float a3 = Arow1[(k8 + 4 + tig) ^ sxa];
                #pragma unroll
                for (int nt = 0; nt < 2; nt++) {
                    int wr = gw * 16 + nt * 8 + gid;
                    const float* Wb = Wsm + (size_t)wr * HH + cc * 32;
                    float b0 = Wb[(k8 + tig) ^ sxa];
                    float b1 = Wb[(k8 + 4 + tig) ^ sxa];
                    mma8(acc[nt], FU(a0), FU(a1), FU(a2), FU(a3), FU(b0), FU(b1));
                }
            }
        }
        __syncthreads();   // all reads of Ah done before sg overlay

        // stage partial gate outputs: [kh][gate][64][17]
        {
            float* sgp = sg + ((size_t)kh * 3 + gw) * 64 * 17;
            #pragma unroll
            for (int nt = 0; nt < 2; nt++) {
                int col = nt * 8 + tig * 2;
                sgp[arow * 17 + col]     = acc[nt][0];
                sgp[arow * 17 + col + 1] = acc[nt][1];
                sgp[(arow + 8) * 17 + col]     = acc[nt][2];
                sgp[(arow + 8) * 17 + col + 1] = acc[nt][3];
            }
        }
        __syncthreads();

        for (int i = tid; i < 1024; i += 768) {
            int row = i >> 4, col = i & 15;
            int bidx = rt * 64 + row;
            int gcol = ct * 16 + col;
            float hr = sg[0 * 64 * 17 + row * 17 + col] + sg[(3 + 0) * 64 * 17 + row * 17 + col] + bhh[gcol];
            float hz = sg[1 * 64 * 17 + row * 17 + col] + sg[(3 + 1) * 64 * 17 + row * 17 + col] + bhh[HH + gcol];
            float hn = sg[2 * 64 * 17 + row * 17 + col] + sg[(3 + 2) * 64 * 17 + row * 17 + col] + bhh[2 * HH + gcol];
            const float* xrow = xg + ((size_t)tt * BB + bidx) * GG;
            float xr = xrow[gcol], xz = xrow[HH + gcol], xn = xrow[2 * HH + gcol];
            float hp = __ldcg(src + (size_t)(rowbase + row) * HH + gcol);
            float rr = 1.f / (1.f + expf(-(xr + hr)));
            float zz = 1.f / (1.f + expf(-(xz + hz)));
            float nn = tanhf(xn + rr * hn);
            float hnew = (1.f - zz) * nn + zz * hp;
            dst[(size_t)(rowbase + row) * HH + gcol] = hnew;
            y[((size_t)tt * BB + bidx) * DD1 + dir * HH + gcol] = cvt_tf32(hnew);
            if (t == SS - 1)
                hid_out[((size_t)dir * BB + bidx) * HH + gcol] = hnew;
        }

        if (t < SS - 1) group_barrier(grp, &ls);
    }
}

// ---------------- host orchestration ----------------
extern "C" void kernel_launch(void* const* d_in, const int* in_sizes, int n_in,
                              void* d_out, int out_size) {
    const int*   i1    = (const int*)d_in[0];
    const int*   i2    = (const int*)d_in[1];
    const int*   pg    = (const int*)d_in[3];
    const float* emb1  = (const float*)d_in[4];
    const float* emb2  = (const float*)d_in[5];
    const float* wih0f = (const float*)d_in[6];
    const float* whh0f = (const float*)d_in[7];
    const float* bih0f = (const float*)d_in[8];
    const float* bhh0f = (const float*)d_in[9];
    const float* wih0b = (const float*)d_in[10];
    const float* whh0b = (const float*)d_in[11];
    const float* bih0b = (const float*)d_in[12];
    const float* bhh0b = (const float*)d_in[13];
    const float* wih1f = (const float*)d_in[14];
    const float* whh1f = (const float*)d_in[15];
    const float* bih1f = (const float*)d_in[16];
    const float* bhh1f = (const float*)d_in[17];
    const float* wih1b = (const float*)d_in[18];
    const float* whh1b = (const float*)d_in[19];
    const float* bih1b = (const float*)d_in[20];
    const float* bhh1b = (const float*)d_in[21];
    const float* fc1w  = (const float*)d_in[22];
    const float* fc1b  = (const float*)d_in[23];
    const float* fc2w  = (const float*)d_in[24];
    const float* fc2b  = (const float*)d_in[25];
    const float* outw  = (const float*)d_in[26];
    const float* outb  = (const float*)d_in[27];
    float* out = (float*)d_out;

    float *x0, *xgf, *xgb, *y0, *y1, *h0, *h1, *an, *dinv, *node, *node2, *ni, *tmp, *nodeT;
    float *rwih0, *rwih1, *rfc1, *rfc2, *routw;
    cudaGetSymbolAddress((void**)&x0,   g_x0);
    cudaGetSymbolAddress((void**)&xgf,  g_xgf);
    cudaGetSymbolAddress((void**)&xgb,  g_xgb);
    cudaGetSymbolAddress((void**)&y0,   g_y0);
    cudaGetSymbolAddress((void**)&y1,   g_y1);
    cudaGetSymbolAddress((void**)&h0,   g_h0);
    cudaGetSymbolAddress((void**)&h1,   g_h1);
    cudaGetSymbolAddress((void**)&an,   g_an);
    cudaGetSymbolAddress((void**)&dinv, g_dinv);
    cudaGetSymbolAddress((void**)&node, g_node);
    cudaGetSymbolAddress((void**)&node2,g_node2);
    cudaGetSymbolAddress((void**)&ni,   g_ni);
    cudaGetSymbolAddress((void**)&tmp,  g_tmp);
    cudaGetSymbolAddress((void**)&nodeT,g_nodeT);
    cudaGetSymbolAddress((void**)&rwih0,g_wih0);
    cudaGetSymbolAddress((void**)&rwih1,g_wih1);
    cudaGetSymbolAddress((void**)&rfc1, g_fc1);
    cudaGetSymbolAddress((void**)&rfc2, g_fc2);
    cudaGetSymbolAddress((void**)&routw,g_outw);

    cudaFuncSetAttribute(gru_persistent,
                         cudaFuncAttributeMaxDynamicSharedMemorySize, GRU_SMEM);
    cudaFuncSetAttribute(mma_gemm_nt<false,false,true>,
                         cudaFuncAttributeMaxDynamicSharedMemorySize, GEMM_SMEM);
    cudaFuncSetAttribute(mma_gemm_nt<true,false,true>,
                         cudaFuncAttributeMaxDynamicSharedMemorySize, GEMM_SMEM);
    cudaFuncSetAttribute(mma_gemm_nt<true,true,false>,
                         cudaFuncAttributeMaxDynamicSharedMemorySize, GEMM_SMEM);

    float* hid_base = out + (size_t)SB * HH;

    // 0) pre-round weights to tf32 (RNA) once per launch
    round_kernel<<<(GG*EE + 255)/256, 256>>>(wih0f, rwih0, GG*EE);
    round_kernel<<<(GG*EE + 255)/256, 256>>>(wih0b, rwih0 + (size_t)GG*EE, GG*EE);
    round_kernel<<<(GG*DD1 + 255)/256, 256>>>(wih1f, rwih1, GG*DD1);
    round_kernel<<<(GG*DD1 + 255)/256, 256>>>(wih1b, rwih1 + (size_t)GG*DD1, GG*DD1);
    round_kernel<<<(2*HH*HH + 255)/256, 256>>>(fc1w, rfc1, 2*HH*HH);
    round_kernel<<<(2*HH*HH + 255)/256, 256>>>(fc2w, rfc2, 2*HH*HH);
    round_kernel<<<(2*HH*DD1 + 255)/256, 256>>>(outw, routw, 2*HH*DD1);

    // 1) embedding (tf32-rounded)
    embed_kernel<<<(SB * EE + 255) / 256, 256>>>(i1, i2, emb1, emb2, x0);

    // 2) layer0 input gates (fused f+b, N=3072)
    dim3 gG2(2 * GG / 128, SB / 128, 1);
    mma_gemm_nt<false,false,true><<<gG2, 256, GEMM_SMEM>>>(
        x0, nullptr, rwih0, rwih0 + (size_t)GG*EE, bih0f, bih0b,
        xgf, xgb, EE, 0, GG, EE, EE, GG, 0, 0, 0);

    // 3) layer0 recurrence (persistent)
    cudaMemsetAsync(h0, 0, (size_t)2 * BB * HH * sizeof(float));
    gru_persistent<<<128, 768, GRU_SMEM>>>(xgf, xgb, whh0f, whh0b, bhh0f, bhh0b,
                                           h0, h1, y0, hid_base);

    // 4) layer1 input gates (fused f+b)
    mma_gemm_nt<false,false,true><<<gG2, 256, GEMM_SMEM>>>(
        y0, nullptr, rwih1, rwih1 + (size_t)GG*DD1, bih1f, bih1b,
        xgf, xgb, DD1, 0, GG, DD1, DD1, GG, 0, 0, 0);

    // 5) layer1 recurrence
    cudaMemsetAsync(h0, 0, (size_t)2 * BB * HH * sizeof(float));
    gru_persistent<<<128, 768, GRU_SMEM>>>(xgf, xgb, whh1f, whh1b, bhh1f, bhh1b,
                                           h0, h1, y1, hid_base + 2 * BB * HH);

    // 6) direction sum -> node [B,S,H] (rounded)
    sumdir_kernel<<<(BB * SS * HH + 255) / 256, 256>>>(y1, node);

    // 7) normalized adjacency (rounded)
    dinv_kernel<<<BB * SS / 8, 256>>>(pg, dinv);
    an_kernel<<<(BB * SS * SS + 255) / 256, 256>>>(pg, dinv, an);

    // 8) GNN hops
    dim3 gH(HH / 128, SB / 128, 1);
    dim3 gAn(HH / 128, SS / 128, BB);
    dim3 gT(HH / 32, SS / 32, BB);
    float* cur = node; float* nxt = node2;
    for (int i = 0; i < 2; i++) {
        const float* f1w = rfc1 + (size_t)i * HH * HH;
        const float* f1b = fc1b + (size_t)i * HH;
        const float* f2w = rfc2 + (size_t)i * HH * HH;
        const float* f2b = fc2b + (size_t)i * HH;
        const float* ow  = routw + (size_t)i * HH * DD1;
        const float* ob  = outb + (size_t)i * HH;

        transpose_bsh<<<gT, dim3(32, 8)>>>(cur, nodeT);
        mma_gemm_nt<false,false,true><<<gAn, 256, GEMM_SMEM>>>(
            an, nullptr, nodeT, nullptr, nullptr, nullptr, tmp, nullptr,
            SS, 0, 0, SS, SS, HH,
            (long long)SS * SS, (long long)HH * SS, (long long)SS * HH);
        mma_gemm_nt<true,false,true><<<gH, 256, GEMM_SMEM>>>(
            tmp, nullptr, f1w, nullptr, f1b, nullptr, ni, nullptr,
            HH, 0, 0, HH, HH, HH, 0, 0, 0);

        transpose_bsh<<<gT, dim3(32, 8)>>>(ni, nodeT);
        mma_gemm_nt<false,false,true><<<gAn, 256, GEMM_SMEM>>>(
            an, nullptr, nodeT, nullptr, nullptr, nullptr, tmp, nullptr,
            SS, 0, 0, SS, SS, HH,
            (long long)SS * SS, (long long)HH * SS, (long long)SS * HH);
        mma_gemm_nt<true,false,true><<<gH, 256, GEMM_SMEM>>>(
            tmp, nullptr, f2w, nullptr, f2b, nullptr, ni, nullptr,
            HH, 0, 0, HH, HH, HH, 0, 0, 0);

        // fused: out = relu([cur|ni] @ ow^T + ob), K=1024, split at 512
        if (i == 0) {
            mma_gemm_nt<true,false,true><<<gH, 256, GEMM_SMEM>>>(
                cur, ni, ow, nullptr, ob, nullptr, nxt, nullptr,
                DD1, HH, 0, HH, DD1, HH, 0, 0, 0);
            float* tptr = cur; cur = nxt; nxt = tptr;
        } else {
            // final hop: write pade_outputs [S,B,H] directly, exact fp32
            mma_gemm_nt<true,true,false><<<gH, 256, GEMM_SMEM>>>(
                cur, ni, ow, nullptr, ob, nullptr, out, nullptr,
                DD1, HH, 0, HH, DD1, HH, 0, 0, 0);
        }
    }
}